// round 3
// baseline (speedup 1.0000x reference)
#include <cuda_runtime.h>
#include <math.h>
#include <stdint.h>

// Problem constants
#define NN 50000
#define EE 800000
#define ETOT (EE + NN)      // edges + self loops
#define FD 128              // H*C = 128 features
#define NCLS 10
#define SLOPE 0.2f

// ---------------- scratch (static device allocations; no cudaMalloc) ----------
__device__ float g_xl[NN * FD];     // source-transformed features (Wl)
__device__ float g_xr[NN * FD];     // target-transformed features (Wr)
__device__ float g_h[NN * FD];      // layer output / next layer input
__device__ int   g_deg[NN];
__device__ int   g_off[NN];
__device__ int   g_cur[NN];
__device__ int   g_csr[ETOT];       // src node id per CSR slot (grouped by dst)
#define NCHUNK 49                   // ceil(50000/1024)
__device__ int   g_chunk[NCHUNK];

// ---------------- CSR construction -------------------------------------------
__global__ void k_init_deg() {
    int i = blockIdx.x * blockDim.x + threadIdx.x;
    if (i < NN) g_deg[i] = 1;       // self loop
}

__global__ void k_count(const int* __restrict__ ei) {
    int i = blockIdx.x * blockDim.x + threadIdx.x;
    if (i < EE) atomicAdd(&g_deg[ei[EE + i]], 1);   // dst row
}

__global__ void k_scan1() {
    __shared__ int sh[1024];
    int i = blockIdx.x * 1024 + threadIdx.x;
    int v = (i < NN) ? g_deg[i] : 0;
    sh[threadIdx.x] = v;
    __syncthreads();
    for (int ofs = 1; ofs < 1024; ofs <<= 1) {
        int t = (threadIdx.x >= ofs) ? sh[threadIdx.x - ofs] : 0;
        __syncthreads();
        sh[threadIdx.x] += t;
        __syncthreads();
    }
    if (i < NN) g_off[i] = sh[threadIdx.x];         // inclusive within chunk
    if (threadIdx.x == 1023) g_chunk[blockIdx.x] = sh[1023];
}

__global__ void k_scan2() {
    // single thread: exclusive scan of chunk totals (49 elements)
    int run = 0;
    for (int c = 0; c < NCHUNK; c++) { int t = g_chunk[c]; g_chunk[c] = run; run += t; }
}

__global__ void k_scan3() {
    int i = blockIdx.x * blockDim.x + threadIdx.x;
    if (i < NN) {
        int start = g_off[i] - g_deg[i] + g_chunk[i >> 10];  // exclusive global start
        g_off[i] = start;
        g_cur[i] = start;
    }
}

__global__ void k_fill(const int* __restrict__ ei) {
    int i = blockIdx.x * blockDim.x + threadIdx.x;
    if (i >= ETOT) return;
    int s, d;
    if (i < EE) { s = ei[i]; d = ei[EE + i]; }
    else        { s = d = i - EE; }
    int p = atomicAdd(&g_cur[d], 1);
    g_csr[p] = s;
}

// ---------------- fused dual GEMM: O = X(nrows x 128) @ W(128 x 128) ----------
// blockIdx.y selects (W0->O0) or (W1->O1). Tile 128x128, K=128 fully resident.
// 256 threads, 8x8 register tile per thread. smem: Xs transposed [k][r], Ws [k][c].
__global__ void k_gemm128(const float* __restrict__ X,
                          const float* __restrict__ W0, const float* __restrict__ W1,
                          float* __restrict__ O0, float* __restrict__ O1,
                          int nrows) {
    extern __shared__ float sm[];
    float* Xs = sm;            // 16384 floats, Xs[k*128 + r]
    float* Ws = sm + 16384;    // 16384 floats, Ws[k*128 + c]
    const float* W = blockIdx.y ? W1 : W0;
    float*       O = blockIdx.y ? O1 : O0;
    int r0  = blockIdx.x * 128;
    int tid = threadIdx.x;

    // load W (row-major [k][c], direct copy)
    const float4* W4 = (const float4*)W;
    float4* Ws4 = (float4*)Ws;
#pragma unroll
    for (int t = 0; t < 16; t++) Ws4[tid + t * 256] = W4[tid + t * 256];

    // load X tile transposed into Xs[k][r]
    const float4* X4 = (const float4*)X;
#pragma unroll
    for (int t = 0; t < 16; t++) {
        int idx = tid + t * 256;            // 0..4095 float4 slots
        int r = idx >> 5, kc = idx & 31;
        float4 v = make_float4(0.f, 0.f, 0.f, 0.f);
        if (r0 + r < nrows) v = X4[(size_t)(r0 + r) * 32 + kc];
        Xs[(kc * 4 + 0) * 128 + r] = v.x;
        Xs[(kc * 4 + 1) * 128 + r] = v.y;
        Xs[(kc * 4 + 2) * 128 + r] = v.z;
        Xs[(kc * 4 + 3) * 128 + r] = v.w;
    }
    __syncthreads();

    int tx = tid & 15, ty = tid >> 4;
    float acc[8][8];
#pragma unroll
    for (int i = 0; i < 8; i++)
#pragma unroll
        for (int j = 0; j < 8; j++) acc[i][j] = 0.f;

    const float* Xp = Xs + ty * 8;
    const float* Wp = Ws + tx * 8;
#pragma unroll 8
    for (int k = 0; k < 128; k++) {
        float4 a0 = *(const float4*)(Xp + k * 128);
        float4 a1 = *(const float4*)(Xp + k * 128 + 4);
        float4 b0 = *(const float4*)(Wp + k * 128);
        float4 b1 = *(const float4*)(Wp + k * 128 + 4);
        float a[8] = {a0.x, a0.y, a0.z, a0.w, a1.x, a1.y, a1.z, a1.w};
        float b[8] = {b0.x, b0.y, b0.z, b0.w, b1.x, b1.y, b1.z, b1.w};
#pragma unroll
        for (int i = 0; i < 8; i++)
#pragma unroll
            for (int j = 0; j < 8; j++) acc[i][j] += a[i] * b[j];
    }

#pragma unroll
    for (int i = 0; i < 8; i++) {
        int r = r0 + ty * 8 + i;
        if (r < nrows) {
            float4 o0 = make_float4(acc[i][0], acc[i][1], acc[i][2], acc[i][3]);
            float4 o1 = make_float4(acc[i][4], acc[i][5], acc[i][6], acc[i][7]);
            ((float4*)O)[(size_t)r * 32 + tx * 2]     = o0;
            ((float4*)O)[(size_t)r * 32 + tx * 2 + 1] = o1;
        }
    }
}

// ---------------- GATv2 edge phase: warp per dst node, online softmax ---------
// lane l owns features [4l, 4l+4); head = l>>2 (4 lanes per head).
// att index for lane l is simply att[4l .. 4l+3].
__global__ void k_gat_aggregate(const float* __restrict__ xl,
                                const float* __restrict__ xr,
                                const float* __restrict__ att,
                                const float* __restrict__ bias,
                                float* __restrict__ out) {
    int gtid = blockIdx.x * blockDim.x + threadIdx.x;
    int v = gtid >> 5;
    int l = threadIdx.x & 31;
    if (v >= NN) return;

    float4 xr4 = *(const float4*)(xr + (size_t)v * FD + l * 4);
    float4 a4  = *(const float4*)(att + l * 4);
    int beg = g_off[v];
    int cnt = g_deg[v];                       // >= 1 (self loop)

    float m = -1e30f, den = 0.f;
    float4 acc = make_float4(0.f, 0.f, 0.f, 0.f);

    int sn = g_csr[beg];
    float4 xn = *(const float4*)(xl + (size_t)sn * FD + l * 4);

    for (int j = 0; j < cnt; j++) {
        float4 xv = xn;
        if (j + 1 < cnt) {                    // prefetch next source row
            int s2 = g_csr[beg + j + 1];
            xn = *(const float4*)(xl + (size_t)s2 * FD + l * 4);
        }
        float ex = xv.x + xr4.x; ex = (ex > 0.f) ? ex : SLOPE * ex;
        float ey = xv.y + xr4.y; ey = (ey > 0.f) ? ey : SLOPE * ey;
        float ez = xv.z + xr4.z; ez = (ez > 0.f) ? ez : SLOPE * ez;
        float ew = xv.w + xr4.w; ew = (ew > 0.f) ? ew : SLOPE * ew;
        float p = ex * a4.x + ey * a4.y + ez * a4.z + ew * a4.w;
        // reduce within 4-lane head group (xor 1, 2 stay in group)
        p += __shfl_xor_sync(0xffffffffu, p, 1);
        p += __shfl_xor_sync(0xffffffffu, p, 2);
        // online softmax update
        float nm = fmaxf(m, p);
        float wo = __expf(m - nm);
        float wn = __expf(p - nm);
        den = den * wo + wn;
        acc.x = acc.x * wo + wn * xv.x;
        acc.y = acc.y * wo + wn * xv.y;
        acc.z = acc.z * wo + wn * xv.z;
        acc.w = acc.w * wo + wn * xv.w;
        m = nm;
    }

    float inv = 1.0f / den;
    float4 b4 = *(const float4*)(bias + l * 4);
    float4 o;
    o.x = fmaxf(acc.x * inv + b4.x, 0.f);     // fused bias + relu
    o.y = fmaxf(acc.y * inv + b4.y, 0.f);
    o.z = fmaxf(acc.z * inv + b4.z, 0.f);
    o.w = fmaxf(acc.w * inv + b4.w, 0.f);
    *(float4*)(out + (size_t)v * FD + l * 4) = o;
}

// ---------------- final fc: out[N][10] = h[N][128] @ Wfc + bfc ----------------
__global__ void k_fc(const float* __restrict__ h,
                     const float* __restrict__ Wfc,
                     const float* __restrict__ bfc,
                     float* __restrict__ out) {
    __shared__ float Ws[FD * NCLS];
    __shared__ float bs[NCLS];
    for (int i = threadIdx.x; i < FD * NCLS; i += blockDim.x) Ws[i] = Wfc[i];
    if (threadIdx.x < NCLS) bs[threadIdx.x] = bfc[threadIdx.x];
    __syncthreads();

    int wid = blockIdx.x * (blockDim.x >> 5) + (threadIdx.x >> 5);
    int l = threadIdx.x & 31;
    if (wid >= NN) return;

    float4 hv = *(const float4*)(h + (size_t)wid * FD + l * 4);
#pragma unroll
    for (int c = 0; c < NCLS; c++) {
        float p = hv.x * Ws[(l * 4 + 0) * NCLS + c]
                + hv.y * Ws[(l * 4 + 1) * NCLS + c]
                + hv.z * Ws[(l * 4 + 2) * NCLS + c]
                + hv.w * Ws[(l * 4 + 3) * NCLS + c];
        p += __shfl_xor_sync(0xffffffffu, p, 16);
        p += __shfl_xor_sync(0xffffffffu, p, 8);
        p += __shfl_xor_sync(0xffffffffu, p, 4);
        p += __shfl_xor_sync(0xffffffffu, p, 2);
        p += __shfl_xor_sync(0xffffffffu, p, 1);
        if (l == c) out[(size_t)wid * NCLS + c] = p + bs[c];
    }
}

// ---------------- launch ------------------------------------------------------
extern "C" void kernel_launch(void* const* d_in, const int* in_sizes, int n_in,
                              void* d_out, int out_size) {
    const float* x    = (const float*)d_in[0];
    const int*   ei   = (const int*)  d_in[1];
    const float* Wl1  = (const float*)d_in[2];
    const float* Wr1  = (const float*)d_in[3];
    const float* att1 = (const float*)d_in[4];
    const float* b1   = (const float*)d_in[5];
    const float* Wl2  = (const float*)d_in[6];
    const float* Wr2  = (const float*)d_in[7];
    const float* att2 = (const float*)d_in[8];
    const float* b2   = (const float*)d_in[9];
    const float* Wfc  = (const float*)d_in[10];
    const float* bfc  = (const float*)d_in[11];
    float* out = (float*)d_out;

    float *xl_p, *xr_p, *h_p;
    cudaGetSymbolAddress((void**)&xl_p, g_xl);
    cudaGetSymbolAddress((void**)&xr_p, g_xr);
    cudaGetSymbolAddress((void**)&h_p,  g_h);

    cudaFuncSetAttribute(k_gemm128, cudaFuncAttributeMaxDynamicSharedMemorySize, 131072);

    // ---- CSR build (edges identical for both layers: build once per launch)
    k_init_deg<<<(NN + 255) / 256, 256>>>();
    k_count<<<(EE + 255) / 256, 256>>>(ei);
    k_scan1<<<NCHUNK, 1024>>>();
    k_scan2<<<1, 1>>>();
    k_scan3<<<(NN + 255) / 256, 256>>>();
    k_fill<<<(ETOT + 255) / 256, 256>>>(ei);

    dim3 ggrid((NN + 127) / 128, 2);
    int  egrid = (NN * 32 + 255) / 256;
    int  fgrid = (NN + 7) / 8;

    // ---- layer 1
    k_gemm128<<<ggrid, 256, 131072>>>(x, Wl1, Wr1, xl_p, xr_p, NN);
    k_gat_aggregate<<<egrid, 256>>>(xl_p, xr_p, att1, b1, h_p);
    // ---- layer 2
    k_gemm128<<<ggrid, 256, 131072>>>(h_p, Wl2, Wr2, xl_p, xr_p, NN);
    k_gat_aggregate<<<egrid, 256>>>(xl_p, xr_p, att2, b2, h_p);
    // ---- fc_out
    k_fc<<<fgrid, 256>>>(h_p, Wfc, bfc, out);
}

// round 6
// speedup vs baseline: 1.4572x; 1.4572x over previous
#include <cuda_runtime.h>
#include <cuda_bf16.h>
#include <math.h>
#include <stdint.h>

// Problem constants
#define NN 50000
#define EE 800000
#define ETOT (EE + NN)      // edges + self loops
#define FD 128              // H*C = 128 features
#define NCLS 10
#define SLOPE 0.2f

// ---------------- scratch (static device allocations; no cudaMalloc) ----------
__device__ float g_xl[NN * FD];     // source-transformed features (Wl)
__device__ float g_xr[NN * FD];     // target-transformed features (Wr)
__device__ float g_h[NN * FD];      // layer output / next layer input
__device__ __nv_bfloat16 g_wh[4][FD * FD];  // weight hi, transposed [n][k]
__device__ __nv_bfloat16 g_wl[4][FD * FD];  // weight lo, transposed [n][k]
__device__ int   g_deg[NN];
__device__ int   g_off[NN];
__device__ int   g_cur[NN];
__device__ int   g_csr[ETOT];       // src node id per CSR slot (grouped by dst)
#define NCHUNK 49                   // ceil(50000/1024)
__device__ int   g_chunk[NCHUNK];

// ---------------- CSR construction -------------------------------------------
__global__ void k_init_deg() {
    int i = blockIdx.x * blockDim.x + threadIdx.x;
    if (i < NN) g_deg[i] = 1;       // self loop
}

__global__ void k_count(const int* __restrict__ ei) {
    int i = blockIdx.x * blockDim.x + threadIdx.x;
    if (i < EE) atomicAdd(&g_deg[ei[EE + i]], 1);   // dst row
}

__global__ void k_scan1() {
    __shared__ int sh[1024];
    int i = blockIdx.x * 1024 + threadIdx.x;
    int v = (i < NN) ? g_deg[i] : 0;
    sh[threadIdx.x] = v;
    __syncthreads();
    for (int ofs = 1; ofs < 1024; ofs <<= 1) {
        int t = (threadIdx.x >= ofs) ? sh[threadIdx.x - ofs] : 0;
        __syncthreads();
        sh[threadIdx.x] += t;
        __syncthreads();
    }
    if (i < NN) g_off[i] = sh[threadIdx.x];         // inclusive within chunk
    if (threadIdx.x == 1023) g_chunk[blockIdx.x] = sh[1023];
}

__global__ void k_scan2() {                          // 64-thread parallel scan
    __shared__ int sh[64];
    int t = threadIdx.x;
    int orig = (t < NCHUNK) ? g_chunk[t] : 0;
    sh[t] = orig;
    __syncthreads();
    for (int ofs = 1; ofs < 64; ofs <<= 1) {
        int v = (t >= ofs) ? sh[t - ofs] : 0;
        __syncthreads();
        sh[t] += v;
        __syncthreads();
    }
    if (t < NCHUNK) g_chunk[t] = sh[t] - orig;       // exclusive
}

__global__ void k_scan3() {
    int i = blockIdx.x * blockDim.x + threadIdx.x;
    if (i < NN) {
        int start = g_off[i] - g_deg[i] + g_chunk[i >> 10];  // exclusive global start
        g_off[i] = start;
        g_cur[i] = start;
    }
}

__global__ void k_fill(const int* __restrict__ ei) {
    int i = blockIdx.x * blockDim.x + threadIdx.x;
    if (i >= ETOT) return;
    int s, d;
    if (i < EE) { s = ei[i]; d = ei[EE + i]; }
    else        { s = d = i - EE; }
    int p = atomicAdd(&g_cur[d], 1);
    g_csr[p] = s;
}

// ---------------- weight prep: split to bf16 hi/lo, transpose to [n][k] ------
__global__ void k_prep_w(const float* __restrict__ Wa, const float* __restrict__ Wb,
                         const float* __restrict__ Wc, const float* __restrict__ Wd) {
    const float* W = (blockIdx.x == 0) ? Wa : (blockIdx.x == 1) ? Wb
                   : (blockIdx.x == 2) ? Wc : Wd;
    __nv_bfloat16* Oh = g_wh[blockIdx.x];
    __nv_bfloat16* Ol = g_wl[blockIdx.x];
    for (int e = threadIdx.x; e < FD * FD; e += blockDim.x) {
        int k = e >> 7, n = e & 127;      // W row-major [k][n]
        float v = W[e];
        __nv_bfloat16 h = __float2bfloat16(v);
        __nv_bfloat16 l = __float2bfloat16(v - __bfloat162float(h));
        Oh[n * 128 + k] = h;
        Ol[n * 128 + k] = l;
    }
}

// ---------------- bf16x3 mma.sync dual GEMM ----------------------------------
// One CTA: 128 rows of X, outputs O0 = X@W0 and O1 = X@W1 (both 128 cols).
// SMEM (bf16, pitch 136 elems): [Ah][Al][B0h][B0l][B1h][B1l], 34816 B each.
#define APITCH 136
#define AB     (128 * APITCH * 2)     // 34816 bytes per array
#define SMEM_GEMM (6 * AB)            // 208896

#define MMA16816(c, a, b0, b1)                                             \
    asm volatile("mma.sync.aligned.m16n8k16.row.col.f32.bf16.bf16.f32 "    \
                 "{%0,%1,%2,%3}, {%4,%5,%6,%7}, {%8,%9}, {%0,%1,%2,%3};"   \
                 : "+f"(c[0]), "+f"(c[1]), "+f"(c[2]), "+f"(c[3])          \
                 : "r"(a[0]), "r"(a[1]), "r"(a[2]), "r"(a[3]),             \
                   "r"(b0), "r"(b1))

__global__ __launch_bounds__(256, 1)
void k_gemm_mma(const float* __restrict__ X,
                const __nv_bfloat16* __restrict__ W0h, const __nv_bfloat16* __restrict__ W0l,
                const __nv_bfloat16* __restrict__ W1h, const __nv_bfloat16* __restrict__ W1l,
                float* __restrict__ O0, float* __restrict__ O1) {
    extern __shared__ char sm[];
    __nv_bfloat16* Ah = (__nv_bfloat16*)(sm);
    __nv_bfloat16* Al = (__nv_bfloat16*)(sm + AB);
    int tid = threadIdx.x;
    int r0 = blockIdx.x * 128;

    // ---- load X tile, split into hi/lo bf16
    const float4* X4 = (const float4*)X;
#pragma unroll
    for (int j = 0; j < 16; j++) {
        int e = tid + j * 256;            // 0..4095
        int row = e >> 5, q = e & 31;     // q = float4 index, k = 4q
        float4 v = make_float4(0.f, 0.f, 0.f, 0.f);
        if (r0 + row < NN) v = X4[(size_t)(r0 + row) * 32 + q];
        __nv_bfloat16 h0 = __float2bfloat16(v.x), h1 = __float2bfloat16(v.y);
        __nv_bfloat16 h2 = __float2bfloat16(v.z), h3 = __float2bfloat16(v.w);
        __nv_bfloat16 l0 = __float2bfloat16(v.x - __bfloat162float(h0));
        __nv_bfloat16 l1 = __float2bfloat16(v.y - __bfloat162float(h1));
        __nv_bfloat16 l2 = __float2bfloat16(v.z - __bfloat162float(h2));
        __nv_bfloat16 l3 = __float2bfloat16(v.w - __bfloat162float(h3));
        int base = row * APITCH + q * 4;
        *(uint32_t*)&Ah[base]     = ((uint32_t)__bfloat16_as_ushort(h1) << 16) | __bfloat16_as_ushort(h0);
        *(uint32_t*)&Ah[base + 2] = ((uint32_t)__bfloat16_as_ushort(h3) << 16) | __bfloat16_as_ushort(h2);
        *(uint32_t*)&Al[base]     = ((uint32_t)__bfloat16_as_ushort(l1) << 16) | __bfloat16_as_ushort(l0);
        *(uint32_t*)&Al[base + 2] = ((uint32_t)__bfloat16_as_ushort(l3) << 16) | __bfloat16_as_ushort(l2);
    }

    // ---- copy weights (dense [n][128] bf16) into pitched SMEM
    {
        const uint4* src[4] = {(const uint4*)W0h, (const uint4*)W0l,
                               (const uint4*)W1h, (const uint4*)W1l};
#pragma unroll
        for (int a = 0; a < 4; a++) {
            char* dst = sm + (2 + a) * AB;
#pragma unroll
            for (int j = 0; j < 8; j++) {
                int e = tid + j * 256;        // 0..2047 uint4
                int n = e >> 4, kq = e & 15;  // kq*8 bf16 = 16 B
                *(uint4*)(dst + n * (APITCH * 2) + kq * 16) = src[a][e];
            }
        }
    }
    __syncthreads();

    // ---- warp layout: 2 (M) x 4 (N); warp tile 64 x 64
    int lane = tid & 31, wid = tid >> 5;
    int g = lane >> 2, t = lane & 3;
    int wm = (wid & 1) * 64;
    int wn = wid >> 1;                    // 0..3
    int bsel = wn >> 1;                   // 0 -> W0, 1 -> W1
    int nb = (wn & 1) * 64;               // col base within the 128-col output
    const __nv_bfloat16* Bh = (const __nv_bfloat16*)(sm + (2 + 2 * bsel) * AB);
    const __nv_bfloat16* Bl = (const __nv_bfloat16*)(sm + (3 + 2 * bsel) * AB);

    float acc[4][8][4];
#pragma unroll
    for (int mi = 0; mi < 4; mi++)
#pragma unroll
        for (int ni = 0; ni < 8; ni++)
#pragma unroll
            for (int q = 0; q < 4; q++) acc[mi][ni][q] = 0.f;

#pragma unroll
    for (int kk = 0; kk < 8; kk++) {
        int k0 = kk * 16;
        uint32_t ah[4][4], al[4][4];
#pragma unroll
        for (int mi = 0; mi < 4; mi++) {
            int rb = wm + mi * 16;
            ah[mi][0] = *(const uint32_t*)&Ah[(rb + g)     * APITCH + k0 + 2 * t];
            ah[mi][1] = *(const uint32_t*)&Ah[(rb + g + 8) * APITCH + k0 + 2 * t];
            ah[mi][2] = *(const uint32_t*)&Ah[(rb + g)     * APITCH + k0 + 2 * t + 8];
            ah[mi][3] = *(const uint32_t*)&Ah[(rb + g + 8) * APITCH + k0 + 2 * t + 8];
            al[mi][0] = *(const uint32_t*)&Al[(rb + g)     * APITCH + k0 + 2 * t];
            al[mi][1] = *(const uint32_t*)&Al[(rb + g + 8) * APITCH + k0 + 2 * t];
            al[mi][2] = *(const uint32_t*)&Al[(rb + g)     * APITCH + k0 + 2 * t + 8];
            al[mi][3] = *(const uint32_t*)&Al[(rb + g + 8) * APITCH + k0 + 2 * t + 8];
        }
#pragma unroll
        for (int ni = 0; ni < 8; ni++) {
            int col = nb + ni * 8 + g;
            uint32_t bh0 = *(const uint32_t*)&Bh[col * APITCH + k0 + 2 * t];
            uint32_t bh1 = *(const uint32_t*)&Bh[col * APITCH + k0 + 2 * t + 8];
            uint32_t bl0 = *(const uint32_t*)&Bl[col * APITCH + k0 + 2 * t];
            uint32_t bl1 = *(const uint32_t*)&Bl[col * APITCH + k0 + 2 * t + 8];
#pragma unroll
            for (int mi = 0; mi < 4; mi++) {
                MMA16816(acc[mi][ni], ah[mi], bh0, bh1);   // hi*hi
                MMA16816(acc[mi][ni], ah[mi], bl0, bl1);   // hi*lo
                MMA16816(acc[mi][ni], al[mi], bh0, bh1);   // lo*hi
            }
        }
    }

    // ---- epilogue: c0/c1 -> (row, 2t), c2/c3 -> (row+8, 2t)
    float* O = bsel ? O1 : O0;
#pragma unroll
    for (int mi = 0; mi < 4; mi++) {
        int row = r0 + wm + mi * 16 + g;
#pragma unroll
        for (int ni = 0; ni < 8; ni++) {
            int colg = nb + ni * 8 + 2 * t;
            if (row < NN)
                *(float2*)&O[(size_t)row * FD + colg] =
                    make_float2(acc[mi][ni][0], acc[mi][ni][1]);
            if (row + 8 < NN)
                *(float2*)&O[(size_t)(row + 8) * FD + colg] =
                    make_float2(acc[mi][ni][2], acc[mi][ni][3]);
        }
    }
}

// ---------------- GATv2 edge phase: warp per dst node, online softmax ---------
__global__ void k_gat_aggregate(const float* __restrict__ xl,
                                const float* __restrict__ xr,
                                const float* __restrict__ att,
                                const float* __restrict__ bias,
                                float* __restrict__ out) {
    int gtid = blockIdx.x * blockDim.x + threadIdx.x;
    int v = gtid >> 5;
    int l = threadIdx.x & 31;
    if (v >= NN) return;

    float4 xr4 = *(const float4*)(xr + (size_t)v * FD + l * 4);
    float4 a4  = *(const float4*)(att + l * 4);
    int beg = g_off[v];
    int cnt = g_deg[v];                       // >= 1 (self loop)

    float m = -1e30f, den = 0.f;
    float4 acc = make_float4(0.f, 0.f, 0.f, 0.f);

    int sn = g_csr[beg];
    float4 xn = *(const float4*)(xl + (size_t)sn * FD + l * 4);

    for (int j = 0; j < cnt; j++) {
        float4 xv = xn;
        if (j + 1 < cnt) {                    // prefetch next source row
            int s2 = g_csr[beg + j + 1];
            xn = *(const float4*)(xl + (size_t)s2 * FD + l * 4);
        }
        float ex = xv.x + xr4.x; ex = (ex > 0.f) ? ex : SLOPE * ex;
        float ey = xv.y + xr4.y; ey = (ey > 0.f) ? ey : SLOPE * ey;
        float ez = xv.z + xr4.z; ez = (ez > 0.f) ? ez : SLOPE * ez;
        float ew = xv.w + xr4.w; ew = (ew > 0.f) ? ew : SLOPE * ew;
        float p = ex * a4.x + ey * a4.y + ez * a4.z + ew * a4.w;
        p += __shfl_xor_sync(0xffffffffu, p, 1);
        p += __shfl_xor_sync(0xffffffffu, p, 2);
        float nm = fmaxf(m, p);
        float wo = __expf(m - nm);
        float wn = __expf(p - nm);
        den = den * wo + wn;
        acc.x = acc.x * wo + wn * xv.x;
        acc.y = acc.y * wo + wn * xv.y;
        acc.z = acc.z * wo + wn * xv.z;
        acc.w = acc.w * wo + wn * xv.w;
        m = nm;
    }

    float inv = 1.0f / den;
    float4 b4 = *(const float4*)(bias + l * 4);
    float4 o;
    o.x = fmaxf(acc.x * inv + b4.x, 0.f);
    o.y = fmaxf(acc.y * inv + b4.y, 0.f);
    o.z = fmaxf(acc.z * inv + b4.z, 0.f);
    o.w = fmaxf(acc.w * inv + b4.w, 0.f);
    *(float4*)(out + (size_t)v * FD + l * 4) = o;
}

// ---------------- final fc: out[N][10] = h[N][128] @ Wfc + bfc ----------------
__global__ void k_fc(const float* __restrict__ h,
                     const float* __restrict__ Wfc,
                     const float* __restrict__ bfc,
                     float* __restrict__ out) {
    __shared__ float Ws[FD * NCLS];
    __shared__ float bs[NCLS];
    for (int i = threadIdx.x; i < FD * NCLS; i += blockDim.x) Ws[i] = Wfc[i];
    if (threadIdx.x < NCLS) bs[threadIdx.x] = bfc[threadIdx.x];
    __syncthreads();

    int wid = blockIdx.x * (blockDim.x >> 5) + (threadIdx.x >> 5);
    int l = threadIdx.x & 31;
    if (wid >= NN) return;

    float4 hv = *(const float4*)(h + (size_t)wid * FD + l * 4);
#pragma unroll
    for (int c = 0; c < NCLS; c++) {
        float p = hv.x * Ws[(l * 4 + 0) * NCLS + c]
                + hv.y * Ws[(l * 4 + 1) * NCLS + c]
                + hv.z * Ws[(l * 4 + 2) * NCLS + c]
                + hv.w * Ws[(l * 4 + 3) * NCLS + c];
        p += __shfl_xor_sync(0xffffffffu, p, 16);
        p += __shfl_xor_sync(0xffffffffu, p, 8);
        p += __shfl_xor_sync(0xffffffffu, p, 4);
        p += __shfl_xor_sync(0xffffffffu, p, 2);
        p += __shfl_xor_sync(0xffffffffu, p, 1);
        if (l == c) out[(size_t)wid * NCLS + c] = p + bs[c];
    }
}

// ---------------- launch ------------------------------------------------------
extern "C" void kernel_launch(void* const* d_in, const int* in_sizes, int n_in,
                              void* d_out, int out_size) {
    const float* x    = (const float*)d_in[0];
    const int*   ei   = (const int*)  d_in[1];
    const float* Wl1  = (const float*)d_in[2];
    const float* Wr1  = (const float*)d_in[3];
    const float* att1 = (const float*)d_in[4];
    const float* b1   = (const float*)d_in[5];
    const float* Wl2  = (const float*)d_in[6];
    const float* Wr2  = (const float*)d_in[7];
    const float* att2 = (const float*)d_in[8];
    const float* b2   = (const float*)d_in[9];
    const float* Wfc  = (const float*)d_in[10];
    const float* bfc  = (const float*)d_in[11];
    float* out = (float*)d_out;

    float *xl_p, *xr_p, *h_p;
    __nv_bfloat16 *wh_p, *wl_p;
    cudaGetSymbolAddress((void**)&xl_p, g_xl);
    cudaGetSymbolAddress((void**)&xr_p, g_xr);
    cudaGetSymbolAddress((void**)&h_p,  g_h);
    cudaGetSymbolAddress((void**)&wh_p, g_wh);
    cudaGetSymbolAddress((void**)&wl_p, g_wl);

    cudaFuncSetAttribute(k_gemm_mma, cudaFuncAttributeMaxDynamicSharedMemorySize, SMEM_GEMM);

    // ---- CSR build + weight prep
    k_init_deg<<<(NN + 255) / 256, 256>>>();
    k_count<<<(EE + 255) / 256, 256>>>(ei);
    k_scan1<<<NCHUNK, 1024>>>();
    k_scan2<<<1, 64>>>();
    k_scan3<<<(NN + 255) / 256, 256>>>();
    k_fill<<<(ETOT + 255) / 256, 256>>>(ei);
    k_prep_w<<<4, 256>>>(Wl1, Wr1, Wl2, Wr2);

    int ggrid = (NN + 127) / 128;
    int egrid = (NN * 32 + 255) / 256;
    int fgrid = (NN + 7) / 8;

    const __nv_bfloat16* w0h = wh_p;
    const __nv_bfloat16* w1h = wh_p + FD * FD;
    const __nv_bfloat16* w2h = wh_p + 2 * FD * FD;
    const __nv_bfloat16* w3h = wh_p + 3 * FD * FD;
    const __nv_bfloat16* w0l = wl_p;
    const __nv_bfloat16* w1l = wl_p + FD * FD;
    const __nv_bfloat16* w2l = wl_p + 2 * FD * FD;
    const __nv_bfloat16* w3l = wl_p + 3 * FD * FD;

    // ---- layer 1
    k_gemm_mma<<<ggrid, 256, SMEM_GEMM>>>(x, w0h, w0l, w1h, w1l, xl_p, xr_p);
    k_gat_aggregate<<<egrid, 256>>>(xl_p, xr_p, att1, b1, h_p);
    // ---- layer 2
    k_gemm_mma<<<ggrid, 256, SMEM_GEMM>>>(h_p, w2h, w2l, w3h, w3l, xl_p, xr_p);
    k_gat_aggregate<<<egrid, 256>>>(xl_p, xr_p, att2, b2, h_p);
    // ---- fc_out
    k_fc<<<fgrid, 256>>>(h_p, Wfc, bfc, out);
}

// round 8
// speedup vs baseline: 1.5350x; 1.0534x over previous
#include <cuda_runtime.h>
#include <cuda_bf16.h>
#include <cuda_fp16.h>
#include <math.h>
#include <stdint.h>

// Problem constants
#define NN 50000
#define EE 800000
#define ETOT (EE + NN)      // edges + self loops
#define FD 128              // H*C = 128 features
#define NCLS 10
#define SLOPE 0.2f

// ---------------- scratch (static device allocations; no cudaMalloc) ----------
__device__ __half g_xlh[NN * FD];   // source-transformed features (Wl), fp16
__device__ float g_xr[NN * FD];     // target-transformed features (Wr)
__device__ float g_h[NN * FD];      // layer output / next layer input
__device__ __nv_bfloat16 g_wh[4][FD * FD];  // weight hi, transposed [n][k]
__device__ __nv_bfloat16 g_wl[4][FD * FD];  // weight lo, transposed [n][k]
__device__ int   g_deg[NN];
__device__ int   g_off[NN];
__device__ int   g_cur[NN];
__device__ int   g_csr[ETOT];       // src node id per CSR slot (grouped by dst)
#define NCHUNK 49                   // ceil(50000/1024)
__device__ int   g_chunk[NCHUNK];

// ---------------- CSR construction -------------------------------------------
__global__ void k_init_deg() {
    int i = blockIdx.x * blockDim.x + threadIdx.x;
    if (i < NN) g_deg[i] = 1;       // self loop
}

__global__ void k_count(const int* __restrict__ ei) {
    int i = blockIdx.x * blockDim.x + threadIdx.x;
    if (i < EE) atomicAdd(&g_deg[ei[EE + i]], 1);   // dst row
}

__global__ void k_scan1() {
    __shared__ int sh[1024];
    int i = blockIdx.x * 1024 + threadIdx.x;
    int v = (i < NN) ? g_deg[i] : 0;
    sh[threadIdx.x] = v;
    __syncthreads();
    for (int ofs = 1; ofs < 1024; ofs <<= 1) {
        int t = (threadIdx.x >= ofs) ? sh[threadIdx.x - ofs] : 0;
        __syncthreads();
        sh[threadIdx.x] += t;
        __syncthreads();
    }
    if (i < NN) g_off[i] = sh[threadIdx.x];         // inclusive within chunk
    if (threadIdx.x == 1023) g_chunk[blockIdx.x] = sh[1023];
}

__global__ void k_scan2() {                          // 64-thread parallel scan
    __shared__ int sh[64];
    int t = threadIdx.x;
    int orig = (t < NCHUNK) ? g_chunk[t] : 0;
    sh[t] = orig;
    __syncthreads();
    for (int ofs = 1; ofs < 64; ofs <<= 1) {
        int v = (t >= ofs) ? sh[t - ofs] : 0;
        __syncthreads();
        sh[t] += v;
        __syncthreads();
    }
    if (t < NCHUNK) g_chunk[t] = sh[t] - orig;       // exclusive
}

__global__ void k_scan3() {
    int i = blockIdx.x * blockDim.x + threadIdx.x;
    if (i < NN) {
        int start = g_off[i] - g_deg[i] + g_chunk[i >> 10];  // exclusive global start
        g_off[i] = start;
        g_cur[i] = start;
    }
}

__global__ void k_fill(const int* __restrict__ ei) {
    int i = blockIdx.x * blockDim.x + threadIdx.x;
    if (i >= ETOT) return;
    int s, d;
    if (i < EE) { s = ei[i]; d = ei[EE + i]; }
    else        { s = d = i - EE; }
    int p = atomicAdd(&g_cur[d], 1);
    g_csr[p] = s;
}

// ---------------- weight prep: split to bf16 hi/lo, transpose to [n][k] ------
__global__ void k_prep_w(const float* __restrict__ Wa, const float* __restrict__ Wb,
                         const float* __restrict__ Wc, const float* __restrict__ Wd) {
    const float* W = (blockIdx.x == 0) ? Wa : (blockIdx.x == 1) ? Wb
                   : (blockIdx.x == 2) ? Wc : Wd;
    __nv_bfloat16* Oh = g_wh[blockIdx.x];
    __nv_bfloat16* Ol = g_wl[blockIdx.x];
    for (int e = threadIdx.x; e < FD * FD; e += blockDim.x) {
        int k = e >> 7, n = e & 127;      // W row-major [k][n]
        float v = W[e];
        __nv_bfloat16 h = __float2bfloat16(v);
        __nv_bfloat16 l = __float2bfloat16(v - __bfloat162float(h));
        Oh[n * 128 + k] = h;
        Ol[n * 128 + k] = l;
    }
}

// ---------------- bf16x3 mma.sync dual GEMM ----------------------------------
// One CTA: 128 rows of X; O0 = X@W0 -> fp16 (xl), O1 = X@W1 -> fp32 (xr).
#define APITCH 136
#define AB     (128 * APITCH * 2)     // 34816 bytes per array
#define SMEM_GEMM (6 * AB)            // 208896

#define MMA16816(c, a, b0, b1)                                             \
    asm volatile("mma.sync.aligned.m16n8k16.row.col.f32.bf16.bf16.f32 "    \
                 "{%0,%1,%2,%3}, {%4,%5,%6,%7}, {%8,%9}, {%0,%1,%2,%3};"   \
                 : "+f"(c[0]), "+f"(c[1]), "+f"(c[2]), "+f"(c[3])          \
                 : "r"(a[0]), "r"(a[1]), "r"(a[2]), "r"(a[3]),             \
                   "r"(b0), "r"(b1))

__global__ __launch_bounds__(256, 1)
void k_gemm_mma(const float* __restrict__ X,
                const __nv_bfloat16* __restrict__ W0h, const __nv_bfloat16* __restrict__ W0l,
                const __nv_bfloat16* __restrict__ W1h, const __nv_bfloat16* __restrict__ W1l,
                __half* __restrict__ O0, float* __restrict__ O1) {
    extern __shared__ char sm[];
    __nv_bfloat16* Ah = (__nv_bfloat16*)(sm);
    __nv_bfloat16* Al = (__nv_bfloat16*)(sm + AB);
    int tid = threadIdx.x;
    int r0 = blockIdx.x * 128;

    // ---- load X tile, split into hi/lo bf16
    const float4* X4 = (const float4*)X;
#pragma unroll
    for (int j = 0; j < 16; j++) {
        int e = tid + j * 256;            // 0..4095
        int row = e >> 5, q = e & 31;
        float4 v = make_float4(0.f, 0.f, 0.f, 0.f);
        if (r0 + row < NN) v = X4[(size_t)(r0 + row) * 32 + q];
        __nv_bfloat16 h0 = __float2bfloat16(v.x), h1 = __float2bfloat16(v.y);
        __nv_bfloat16 h2 = __float2bfloat16(v.z), h3 = __float2bfloat16(v.w);
        __nv_bfloat16 l0 = __float2bfloat16(v.x - __bfloat162float(h0));
        __nv_bfloat16 l1 = __float2bfloat16(v.y - __bfloat162float(h1));
        __nv_bfloat16 l2 = __float2bfloat16(v.z - __bfloat162float(h2));
        __nv_bfloat16 l3 = __float2bfloat16(v.w - __bfloat162float(h3));
        int base = row * APITCH + q * 4;
        *(uint32_t*)&Ah[base]     = ((uint32_t)__bfloat16_as_ushort(h1) << 16) | __bfloat16_as_ushort(h0);
        *(uint32_t*)&Ah[base + 2] = ((uint32_t)__bfloat16_as_ushort(h3) << 16) | __bfloat16_as_ushort(h2);
        *(uint32_t*)&Al[base]     = ((uint32_t)__bfloat16_as_ushort(l1) << 16) | __bfloat16_as_ushort(l0);
        *(uint32_t*)&Al[base + 2] = ((uint32_t)__bfloat16_as_ushort(l3) << 16) | __bfloat16_as_ushort(l2);
    }

    // ---- copy weights (dense [n][128] bf16) into pitched SMEM
    {
        const uint4* src[4] = {(const uint4*)W0h, (const uint4*)W0l,
                               (const uint4*)W1h, (const uint4*)W1l};
#pragma unroll
        for (int a = 0; a < 4; a++) {
            char* dst = sm + (2 + a) * AB;
#pragma unroll
            for (int j = 0; j < 8; j++) {
                int e = tid + j * 256;
                int n = e >> 4, kq = e & 15;
                *(uint4*)(dst + n * (APITCH * 2) + kq * 16) = src[a][e];
            }
        }
    }
    __syncthreads();

    // ---- warp layout: 2 (M) x 4 (N); warp tile 64 x 64
    int lane = tid & 31, wid = tid >> 5;
    int g = lane >> 2, t = lane & 3;
    int wm = (wid & 1) * 64;
    int wn = wid >> 1;
    int bsel = wn >> 1;                   // 0 -> W0 (xl/fp16), 1 -> W1 (xr/fp32)
    int nb = (wn & 1) * 64;
    const __nv_bfloat16* Bh = (const __nv_bfloat16*)(sm + (2 + 2 * bsel) * AB);
    const __nv_bfloat16* Bl = (const __nv_bfloat16*)(sm + (3 + 2 * bsel) * AB);

    float acc[4][8][4];
#pragma unroll
    for (int mi = 0; mi < 4; mi++)
#pragma unroll
        for (int ni = 0; ni < 8; ni++)
#pragma unroll
            for (int q = 0; q < 4; q++) acc[mi][ni][q] = 0.f;

#pragma unroll
    for (int kk = 0; kk < 8; kk++) {
        int k0 = kk * 16;
        uint32_t ah[4][4], al[4][4];
#pragma unroll
        for (int mi = 0; mi < 4; mi++) {
            int rb = wm + mi * 16;
            ah[mi][0] = *(const uint32_t*)&Ah[(rb + g)     * APITCH + k0 + 2 * t];
            ah[mi][1] = *(const uint32_t*)&Ah[(rb + g + 8) * APITCH + k0 + 2 * t];
            ah[mi][2] = *(const uint32_t*)&Ah[(rb + g)     * APITCH + k0 + 2 * t + 8];
            ah[mi][3] = *(const uint32_t*)&Ah[(rb + g + 8) * APITCH + k0 + 2 * t + 8];
            al[mi][0] = *(const uint32_t*)&Al[(rb + g)     * APITCH + k0 + 2 * t];
            al[mi][1] = *(const uint32_t*)&Al[(rb + g + 8) * APITCH + k0 + 2 * t];
            al[mi][2] = *(const uint32_t*)&Al[(rb + g)     * APITCH + k0 + 2 * t + 8];
            al[mi][3] = *(const uint32_t*)&Al[(rb + g + 8) * APITCH + k0 + 2 * t + 8];
        }
#pragma unroll
        for (int ni = 0; ni < 8; ni++) {
            int col = nb + ni * 8 + g;
            uint32_t bh0 = *(const uint32_t*)&Bh[col * APITCH + k0 + 2 * t];
            uint32_t bh1 = *(const uint32_t*)&Bh[col * APITCH + k0 + 2 * t + 8];
            uint32_t bl0 = *(const uint32_t*)&Bl[col * APITCH + k0 + 2 * t];
            uint32_t bl1 = *(const uint32_t*)&Bl[col * APITCH + k0 + 2 * t + 8];
#pragma unroll
            for (int mi = 0; mi < 4; mi++) {
                MMA16816(acc[mi][ni], ah[mi], bh0, bh1);   // hi*hi
                MMA16816(acc[mi][ni], ah[mi], bl0, bl1);   // hi*lo
                MMA16816(acc[mi][ni], al[mi], bh0, bh1);   // lo*hi
            }
        }
    }

    // ---- epilogue
#pragma unroll
    for (int mi = 0; mi < 4; mi++) {
        int row = r0 + wm + mi * 16 + g;
#pragma unroll
        for (int ni = 0; ni < 8; ni++) {
            int colg = nb + ni * 8 + 2 * t;
            if (bsel == 0) {
                if (row < NN)
                    *(__half2*)&O0[(size_t)row * FD + colg] =
                        __floats2half2_rn(acc[mi][ni][0], acc[mi][ni][1]);
                if (row + 8 < NN)
                    *(__half2*)&O0[(size_t)(row + 8) * FD + colg] =
                        __floats2half2_rn(acc[mi][ni][2], acc[mi][ni][3]);
            } else {
                if (row < NN)
                    *(float2*)&O1[(size_t)row * FD + colg] =
                        make_float2(acc[mi][ni][0], acc[mi][ni][1]);
                if (row + 8 < NN)
                    *(float2*)&O1[(size_t)(row + 8) * FD + colg] =
                        make_float2(acc[mi][ni][2], acc[mi][ni][3]);
            }
        }
    }
}

// ---------------- GATv2 edge core: warp per dst node, online softmax ----------
// Returns post-bias+relu feature quad for lane l of node v.
__device__ __forceinline__ float4 gat_node(const __half* __restrict__ xl,
                                           const float* __restrict__ xr,
                                           const float* __restrict__ att,
                                           const float* __restrict__ bias,
                                           int v, int l) {
    float4 xr4 = *(const float4*)(xr + (size_t)v * FD + l * 4);
    float4 a4  = *(const float4*)(att + l * 4);
    int beg = g_off[v];
    int cnt = g_deg[v];                       // >= 1 (self loop)

    float m = -1e30f, den = 0.f;
    float4 acc = make_float4(0.f, 0.f, 0.f, 0.f);

    int sn = g_csr[beg];
    uint2 rn = *(const uint2*)(xl + (size_t)sn * FD + l * 4);

    for (int j = 0; j < cnt; j++) {
        uint2 rv = rn;
        if (j + 1 < cnt) {                    // prefetch next source row
            int s2 = g_csr[beg + j + 1];
            rn = *(const uint2*)(xl + (size_t)s2 * FD + l * 4);
        }
        float2 f0 = __half22float2(*(__half2*)&rv.x);
        float2 f1 = __half22float2(*(__half2*)&rv.y);
        float4 xv = make_float4(f0.x, f0.y, f1.x, f1.y);
        float ex = xv.x + xr4.x; ex = (ex > 0.f) ? ex : SLOPE * ex;
        float ey = xv.y + xr4.y; ey = (ey > 0.f) ? ey : SLOPE * ey;
        float ez = xv.z + xr4.z; ez = (ez > 0.f) ? ez : SLOPE * ez;
        float ew = xv.w + xr4.w; ew = (ew > 0.f) ? ew : SLOPE * ew;
        float p = ex * a4.x + ey * a4.y + ez * a4.z + ew * a4.w;
        p += __shfl_xor_sync(0xffffffffu, p, 1);
        p += __shfl_xor_sync(0xffffffffu, p, 2);
        float nm = fmaxf(m, p);
        float wo = __expf(m - nm);
        float wn = __expf(p - nm);
        den = den * wo + wn;
        acc.x = acc.x * wo + wn * xv.x;
        acc.y = acc.y * wo + wn * xv.y;
        acc.z = acc.z * wo + wn * xv.z;
        acc.w = acc.w * wo + wn * xv.w;
        m = nm;
    }

    float inv = 1.0f / den;
    float4 b4 = *(const float4*)(bias + l * 4);
    float4 o;
    o.x = fmaxf(acc.x * inv + b4.x, 0.f);     // fused bias + relu
    o.y = fmaxf(acc.y * inv + b4.y, 0.f);
    o.z = fmaxf(acc.z * inv + b4.z, 0.f);
    o.w = fmaxf(acc.w * inv + b4.w, 0.f);
    return o;
}

__global__ void k_gat_aggregate(const __half* __restrict__ xl,
                                const float* __restrict__ xr,
                                const float* __restrict__ att,
                                const float* __restrict__ bias,
                                float* __restrict__ out) {
    int gtid = blockIdx.x * blockDim.x + threadIdx.x;
    int v = gtid >> 5;
    int l = threadIdx.x & 31;
    if (v >= NN) return;
    float4 o = gat_node(xl, xr, att, bias, v, l);
    *(float4*)(out + (size_t)v * FD + l * 4) = o;
}

// Layer-2 aggregate with fused fc_out epilogue: out[v][c] = relu(h) . Wfc[:,c] + bfc
__global__ void k_gat_fc(const __half* __restrict__ xl,
                         const float* __restrict__ xr,
                         const float* __restrict__ att,
                         const float* __restrict__ bias,
                         const float* __restrict__ Wfc,
                         const float* __restrict__ bfc,
                         float* __restrict__ out) {
    __shared__ float Ws[FD * NCLS];
    __shared__ float bs[NCLS];
    for (int i = threadIdx.x; i < FD * NCLS; i += blockDim.x) Ws[i] = Wfc[i];
    if (threadIdx.x < NCLS) bs[threadIdx.x] = bfc[threadIdx.x];
    __syncthreads();

    int gtid = blockIdx.x * blockDim.x + threadIdx.x;
    int v = gtid >> 5;
    int l = threadIdx.x & 31;
    if (v >= NN) return;
    float4 o = gat_node(xl, xr, att, bias, v, l);

#pragma unroll
    for (int c = 0; c < NCLS; c++) {
        float p = o.x * Ws[(l * 4 + 0) * NCLS + c]
                + o.y * Ws[(l * 4 + 1) * NCLS + c]
                + o.z * Ws[(l * 4 + 2) * NCLS + c]
                + o.w * Ws[(l * 4 + 3) * NCLS + c];
        p += __shfl_xor_sync(0xffffffffu, p, 16);
        p += __shfl_xor_sync(0xffffffffu, p, 8);
        p += __shfl_xor_sync(0xffffffffu, p, 4);
        p += __shfl_xor_sync(0xffffffffu, p, 2);
        p += __shfl_xor_sync(0xffffffffu, p, 1);
        if (l == c) out[(size_t)v * NCLS + c] = p + bs[c];
    }
}

// ---------------- launch ------------------------------------------------------
extern "C" void kernel_launch(void* const* d_in, const int* in_sizes, int n_in,
                              void* d_out, int out_size) {
    const float* x    = (const float*)d_in[0];
    const int*   ei   = (const int*)  d_in[1];
    const float* Wl1  = (const float*)d_in[2];
    const float* Wr1  = (const float*)d_in[3];
    const float* att1 = (const float*)d_in[4];
    const float* b1   = (const float*)d_in[5];
    const float* Wl2  = (const float*)d_in[6];
    const float* Wr2  = (const float*)d_in[7];
    const float* att2 = (const float*)d_in[8];
    const float* b2   = (const float*)d_in[9];
    const float* Wfc  = (const float*)d_in[10];
    const float* bfc  = (const float*)d_in[11];
    float* out = (float*)d_out;

    float *xr_p, *h_p;
    __half *xlh_p;
    __nv_bfloat16 *wh_p, *wl_p;
    cudaGetSymbolAddress((void**)&xlh_p, g_xlh);
    cudaGetSymbolAddress((void**)&xr_p,  g_xr);
    cudaGetSymbolAddress((void**)&h_p,   g_h);
    cudaGetSymbolAddress((void**)&wh_p,  g_wh);
    cudaGetSymbolAddress((void**)&wl_p,  g_wl);

    cudaFuncSetAttribute(k_gemm_mma, cudaFuncAttributeMaxDynamicSharedMemorySize, SMEM_GEMM);

    // ---- CSR build + weight prep
    k_init_deg<<<(NN + 255) / 256, 256>>>();
    k_count<<<(EE + 255) / 256, 256>>>(ei);
    k_scan1<<<NCHUNK, 1024>>>();
    k_scan2<<<1, 64>>>();
    k_scan3<<<(NN + 255) / 256, 256>>>();
    k_fill<<<(ETOT + 255) / 256, 256>>>(ei);
    k_prep_w<<<4, 256>>>(Wl1, Wr1, Wl2, Wr2);

    int ggrid = (NN + 127) / 128;
    int egrid = (NN * 32 + 255) / 256;

    const __nv_bfloat16* w0h = wh_p;
    const __nv_bfloat16* w1h = wh_p + FD * FD;
    const __nv_bfloat16* w2h = wh_p + 2 * FD * FD;
    const __nv_bfloat16* w3h = wh_p + 3 * FD * FD;
    const __nv_bfloat16* w0l = wl_p;
    const __nv_bfloat16* w1l = wl_p + FD * FD;
    const __nv_bfloat16* w2l = wl_p + 2 * FD * FD;
    const __nv_bfloat16* w3l = wl_p + 3 * FD * FD;

    // ---- layer 1
    k_gemm_mma<<<ggrid, 256, SMEM_GEMM>>>(x, w0h, w0l, w1h, w1l, xlh_p, xr_p);
    k_gat_aggregate<<<egrid, 256>>>(xlh_p, xr_p, att1, b1, h_p);
    // ---- layer 2 (fc fused into aggregate epilogue)
    k_gemm_mma<<<ggrid, 256, SMEM_GEMM>>>(h_p, w2h, w2l, w3h, w3l, xlh_p, xr_p);
    k_gat_fc<<<egrid, 256>>>(xlh_p, xr_p, att2, b2, Wfc, bfc, out);
}

// round 9
// speedup vs baseline: 1.5585x; 1.0153x over previous
#include <cuda_runtime.h>
#include <cuda_fp16.h>
#include <math.h>
#include <stdint.h>

// Problem constants
#define NN 50000
#define EE 800000
#define ETOT (EE + NN)      // edges + self loops
#define FD 128              // H*C = 128 features
#define NCLS 10
#define SLOPE 0.2f

// ---------------- scratch (static device allocations; no cudaMalloc) ----------
__device__ __half g_xlh[NN * FD];   // source-transformed features (Wl), fp16
__device__ float g_xr[NN * FD];     // target-transformed features (Wr)
__device__ float g_h[NN * FD];      // layer output / next layer input
__device__ __half g_wf[4][FD * FD]; // fp16 weights, transposed [n][k]
__device__ int   g_deg[NN];
__device__ int   g_off[NN];
__device__ int   g_cur[NN];
__device__ int   g_csr[ETOT];       // src node id per CSR slot (grouped by dst)
#define NCHUNK 49                   // ceil(50000/1024)
__device__ int   g_chunk[NCHUNK];

// ---------------- CSR construction -------------------------------------------
__global__ void k_init_deg() {
    int i = blockIdx.x * blockDim.x + threadIdx.x;
    if (i < NN) g_deg[i] = 1;       // self loop
}

__global__ void k_count(const int* __restrict__ ei) {
    int i = blockIdx.x * blockDim.x + threadIdx.x;
    if (i < EE) atomicAdd(&g_deg[ei[EE + i]], 1);   // dst row
}

__global__ void k_scan1() {
    __shared__ int sh[1024];
    int i = blockIdx.x * 1024 + threadIdx.x;
    int v = (i < NN) ? g_deg[i] : 0;
    sh[threadIdx.x] = v;
    __syncthreads();
    for (int ofs = 1; ofs < 1024; ofs <<= 1) {
        int t = (threadIdx.x >= ofs) ? sh[threadIdx.x - ofs] : 0;
        __syncthreads();
        sh[threadIdx.x] += t;
        __syncthreads();
    }
    if (i < NN) g_off[i] = sh[threadIdx.x];         // inclusive within chunk
    if (threadIdx.x == 1023) g_chunk[blockIdx.x] = sh[1023];
}

__global__ void k_scan2() {                          // 64-thread parallel scan
    __shared__ int sh[64];
    int t = threadIdx.x;
    int orig = (t < NCHUNK) ? g_chunk[t] : 0;
    sh[t] = orig;
    __syncthreads();
    for (int ofs = 1; ofs < 64; ofs <<= 1) {
        int v = (t >= ofs) ? sh[t - ofs] : 0;
        __syncthreads();
        sh[t] += v;
        __syncthreads();
    }
    if (t < NCHUNK) g_chunk[t] = sh[t] - orig;       // exclusive
}

__global__ void k_scan3() {
    int i = blockIdx.x * blockDim.x + threadIdx.x;
    if (i < NN) {
        int start = g_off[i] - g_deg[i] + g_chunk[i >> 10];  // exclusive global start
        g_off[i] = start;
        g_cur[i] = start;
    }
}

__global__ void k_fill(const int* __restrict__ ei) {
    int i = blockIdx.x * blockDim.x + threadIdx.x;
    if (i >= ETOT) return;
    int s, d;
    if (i < EE) { s = ei[i]; d = ei[EE + i]; }
    else        { s = d = i - EE; }
    int p = atomicAdd(&g_cur[d], 1);
    g_csr[p] = s;
}

// ---------------- weight prep: fp16, transposed to [n][k] --------------------
__global__ void k_prep_w(const float* __restrict__ Wa, const float* __restrict__ Wb,
                         const float* __restrict__ Wc, const float* __restrict__ Wd) {
    const float* W = (blockIdx.x == 0) ? Wa : (blockIdx.x == 1) ? Wb
                   : (blockIdx.x == 2) ? Wc : Wd;
    __half* O = g_wf[blockIdx.x];
    for (int e = threadIdx.x; e < FD * FD; e += blockDim.x) {
        int k = e >> 7, n = e & 127;      // W row-major [k][n]
        O[n * 128 + k] = __float2half_rn(W[e]);
    }
}

// ---------------- fp16 mma.sync dual GEMM ------------------------------------
// One CTA: 128 rows of X; O0 = X@W0 -> fp16 (xl), O1 = X@W1 -> fp32 (xr).
// SMEM fp16, pitch 136: [A][W0][W1], 34816 B each = 104448 total -> 2 CTAs/SM.
#define APITCH 136
#define AB     (128 * APITCH * 2)     // 34816 bytes per array
#define SMEM_GEMM (3 * AB)            // 104448

#define MMA16816F(c, a, b0, b1)                                            \
    asm volatile("mma.sync.aligned.m16n8k16.row.col.f32.f16.f16.f32 "      \
                 "{%0,%1,%2,%3}, {%4,%5,%6,%7}, {%8,%9}, {%0,%1,%2,%3};"   \
                 : "+f"(c[0]), "+f"(c[1]), "+f"(c[2]), "+f"(c[3])          \
                 : "r"(a[0]), "r"(a[1]), "r"(a[2]), "r"(a[3]),             \
                   "r"(b0), "r"(b1))

__global__ __launch_bounds__(256, 2)
void k_gemm_mma(const float* __restrict__ X,
                const __half* __restrict__ W0, const __half* __restrict__ W1,
                __half* __restrict__ O0, float* __restrict__ O1) {
    extern __shared__ char sm[];
    __half* A = (__half*)(sm);
    int tid = threadIdx.x;
    int r0 = blockIdx.x * 128;

    // ---- load X tile -> fp16
    const float4* X4 = (const float4*)X;
#pragma unroll
    for (int j = 0; j < 16; j++) {
        int e = tid + j * 256;            // 0..4095
        int row = e >> 5, q = e & 31;
        float4 v = make_float4(0.f, 0.f, 0.f, 0.f);
        if (r0 + row < NN) v = X4[(size_t)(r0 + row) * 32 + q];
        __half2 p0 = __floats2half2_rn(v.x, v.y);
        __half2 p1 = __floats2half2_rn(v.z, v.w);
        int base = row * APITCH + q * 4;
        *(__half2*)&A[base]     = p0;
        *(__half2*)&A[base + 2] = p1;
    }

    // ---- copy weights (dense [n][128] fp16) into pitched SMEM
    {
        const uint4* src[2] = {(const uint4*)W0, (const uint4*)W1};
#pragma unroll
        for (int a = 0; a < 2; a++) {
            char* dst = sm + (1 + a) * AB;
#pragma unroll
            for (int j = 0; j < 8; j++) {
                int e = tid + j * 256;        // 0..2047 uint4
                int n = e >> 4, kq = e & 15;  // kq*8 fp16 = 16 B
                *(uint4*)(dst + n * (APITCH * 2) + kq * 16) = src[a][e];
            }
        }
    }
    __syncthreads();

    // ---- warp layout: 2 (M) x 4 (N); warp tile 64 x 64
    int lane = tid & 31, wid = tid >> 5;
    int g = lane >> 2, t = lane & 3;
    int wm = (wid & 1) * 64;
    int wn = wid >> 1;
    int bsel = wn >> 1;                   // 0 -> W0 (xl/fp16), 1 -> W1 (xr/fp32)
    int nb = (wn & 1) * 64;
    const __half* B = (const __half*)(sm + (1 + bsel) * AB);

    float acc[4][8][4];
#pragma unroll
    for (int mi = 0; mi < 4; mi++)
#pragma unroll
        for (int ni = 0; ni < 8; ni++)
#pragma unroll
            for (int q = 0; q < 4; q++) acc[mi][ni][q] = 0.f;

#pragma unroll
    for (int kk = 0; kk < 8; kk++) {
        int k0 = kk * 16;
        uint32_t ah[4][4];
#pragma unroll
        for (int mi = 0; mi < 4; mi++) {
            int rb = wm + mi * 16;
            ah[mi][0] = *(const uint32_t*)&A[(rb + g)     * APITCH + k0 + 2 * t];
            ah[mi][1] = *(const uint32_t*)&A[(rb + g + 8) * APITCH + k0 + 2 * t];
            ah[mi][2] = *(const uint32_t*)&A[(rb + g)     * APITCH + k0 + 2 * t + 8];
            ah[mi][3] = *(const uint32_t*)&A[(rb + g + 8) * APITCH + k0 + 2 * t + 8];
        }
#pragma unroll
        for (int ni = 0; ni < 8; ni++) {
            int col = nb + ni * 8 + g;
            uint32_t b0 = *(const uint32_t*)&B[col * APITCH + k0 + 2 * t];
            uint32_t b1 = *(const uint32_t*)&B[col * APITCH + k0 + 2 * t + 8];
#pragma unroll
            for (int mi = 0; mi < 4; mi++)
                MMA16816F(acc[mi][ni], ah[mi], b0, b1);
        }
    }

    // ---- epilogue
#pragma unroll
    for (int mi = 0; mi < 4; mi++) {
        int row = r0 + wm + mi * 16 + g;
#pragma unroll
        for (int ni = 0; ni < 8; ni++) {
            int colg = nb + ni * 8 + 2 * t;
            if (bsel == 0) {
                if (row < NN)
                    *(__half2*)&O0[(size_t)row * FD + colg] =
                        __floats2half2_rn(acc[mi][ni][0], acc[mi][ni][1]);
                if (row + 8 < NN)
                    *(__half2*)&O0[(size_t)(row + 8) * FD + colg] =
                        __floats2half2_rn(acc[mi][ni][2], acc[mi][ni][3]);
            } else {
                if (row < NN)
                    *(float2*)&O1[(size_t)row * FD + colg] =
                        make_float2(acc[mi][ni][0], acc[mi][ni][1]);
                if (row + 8 < NN)
                    *(float2*)&O1[(size_t)(row + 8) * FD + colg] =
                        make_float2(acc[mi][ni][2], acc[mi][ni][3]);
            }
        }
    }
}

// ---------------- GATv2 edge core: warp per dst node, online softmax ----------
__device__ __forceinline__ float4 gat_node(const __half* __restrict__ xl,
                                           const float* __restrict__ xr,
                                           const float* __restrict__ att,
                                           const float* __restrict__ bias,
                                           int v, int l) {
    float4 xr4 = *(const float4*)(xr + (size_t)v * FD + l * 4);
    float4 a4  = *(const float4*)(att + l * 4);
    int beg = g_off[v];
    int cnt = g_deg[v];                       // >= 1 (self loop)

    float m = -1e30f, den = 0.f;
    float4 acc = make_float4(0.f, 0.f, 0.f, 0.f);

    int sn = g_csr[beg];
    uint2 rn = *(const uint2*)(xl + (size_t)sn * FD + l * 4);

    for (int j = 0; j < cnt; j++) {
        uint2 rv = rn;
        if (j + 1 < cnt) {                    // prefetch next source row
            int s2 = g_csr[beg + j + 1];
            rn = *(const uint2*)(xl + (size_t)s2 * FD + l * 4);
        }
        float2 f0 = __half22float2(*(__half2*)&rv.x);
        float2 f1 = __half22float2(*(__half2*)&rv.y);
        float4 xv = make_float4(f0.x, f0.y, f1.x, f1.y);
        float ex = xv.x + xr4.x; ex = (ex > 0.f) ? ex : SLOPE * ex;
        float ey = xv.y + xr4.y; ey = (ey > 0.f) ? ey : SLOPE * ey;
        float ez = xv.z + xr4.z; ez = (ez > 0.f) ? ez : SLOPE * ez;
        float ew = xv.w + xr4.w; ew = (ew > 0.f) ? ew : SLOPE * ew;
        float p = ex * a4.x + ey * a4.y + ez * a4.z + ew * a4.w;
        p += __shfl_xor_sync(0xffffffffu, p, 1);
        p += __shfl_xor_sync(0xffffffffu, p, 2);
        float nm = fmaxf(m, p);
        float wo = __expf(m - nm);
        float wn = __expf(p - nm);
        den = den * wo + wn;
        acc.x = acc.x * wo + wn * xv.x;
        acc.y = acc.y * wo + wn * xv.y;
        acc.z = acc.z * wo + wn * xv.z;
        acc.w = acc.w * wo + wn * xv.w;
        m = nm;
    }

    float inv = 1.0f / den;
    float4 b4 = *(const float4*)(bias + l * 4);
    float4 o;
    o.x = fmaxf(acc.x * inv + b4.x, 0.f);     // fused bias + relu
    o.y = fmaxf(acc.y * inv + b4.y, 0.f);
    o.z = fmaxf(acc.z * inv + b4.z, 0.f);
    o.w = fmaxf(acc.w * inv + b4.w, 0.f);
    return o;
}

__global__ void k_gat_aggregate(const __half* __restrict__ xl,
                                const float* __restrict__ xr,
                                const float* __restrict__ att,
                                const float* __restrict__ bias,
                                float* __restrict__ out) {
    int gtid = blockIdx.x * blockDim.x + threadIdx.x;
    int v = gtid >> 5;
    int l = threadIdx.x & 31;
    if (v >= NN) return;
    float4 o = gat_node(xl, xr, att, bias, v, l);
    *(float4*)(out + (size_t)v * FD + l * 4) = o;
}

// Layer-2 aggregate with fused fc_out epilogue
__global__ void k_gat_fc(const __half* __restrict__ xl,
                         const float* __restrict__ xr,
                         const float* __restrict__ att,
                         const float* __restrict__ bias,
                         const float* __restrict__ Wfc,
                         const float* __restrict__ bfc,
                         float* __restrict__ out) {
    __shared__ float Ws[FD * NCLS];
    __shared__ float bs[NCLS];
    for (int i = threadIdx.x; i < FD * NCLS; i += blockDim.x) Ws[i] = Wfc[i];
    if (threadIdx.x < NCLS) bs[threadIdx.x] = bfc[threadIdx.x];
    __syncthreads();

    int gtid = blockIdx.x * blockDim.x + threadIdx.x;
    int v = gtid >> 5;
    int l = threadIdx.x & 31;
    if (v >= NN) return;
    float4 o = gat_node(xl, xr, att, bias, v, l);

#pragma unroll
    for (int c = 0; c < NCLS; c++) {
        float p = o.x * Ws[(l * 4 + 0) * NCLS + c]
                + o.y * Ws[(l * 4 + 1) * NCLS + c]
                + o.z * Ws[(l * 4 + 2) * NCLS + c]
                + o.w * Ws[(l * 4 + 3) * NCLS + c];
        p += __shfl_xor_sync(0xffffffffu, p, 16);
        p += __shfl_xor_sync(0xffffffffu, p, 8);
        p += __shfl_xor_sync(0xffffffffu, p, 4);
        p += __shfl_xor_sync(0xffffffffu, p, 2);
        p += __shfl_xor_sync(0xffffffffu, p, 1);
        if (l == c) out[(size_t)v * NCLS + c] = p + bs[c];
    }
}

// ---------------- launch ------------------------------------------------------
extern "C" void kernel_launch(void* const* d_in, const int* in_sizes, int n_in,
                              void* d_out, int out_size) {
    const float* x    = (const float*)d_in[0];
    const int*   ei   = (const int*)  d_in[1];
    const float* Wl1  = (const float*)d_in[2];
    const float* Wr1  = (const float*)d_in[3];
    const float* att1 = (const float*)d_in[4];
    const float* b1   = (const float*)d_in[5];
    const float* Wl2  = (const float*)d_in[6];
    const float* Wr2  = (const float*)d_in[7];
    const float* att2 = (const float*)d_in[8];
    const float* b2   = (const float*)d_in[9];
    const float* Wfc  = (const float*)d_in[10];
    const float* bfc  = (const float*)d_in[11];
    float* out = (float*)d_out;

    float *xr_p, *h_p;
    __half *xlh_p, *wf_p;
    cudaGetSymbolAddress((void**)&xlh_p, g_xlh);
    cudaGetSymbolAddress((void**)&xr_p,  g_xr);
    cudaGetSymbolAddress((void**)&h_p,   g_h);
    cudaGetSymbolAddress((void**)&wf_p,  g_wf);

    cudaFuncSetAttribute(k_gemm_mma, cudaFuncAttributeMaxDynamicSharedMemorySize, SMEM_GEMM);

    // ---- CSR build + weight prep
    k_init_deg<<<(NN + 255) / 256, 256>>>();
    k_count<<<(EE + 255) / 256, 256>>>(ei);
    k_scan1<<<NCHUNK, 1024>>>();
    k_scan2<<<1, 64>>>();
    k_scan3<<<(NN + 255) / 256, 256>>>();
    k_fill<<<(ETOT + 255) / 256, 256>>>(ei);
    k_prep_w<<<4, 256>>>(Wl1, Wr1, Wl2, Wr2);

    int ggrid = (NN + 127) / 128;
    int egrid = (NN * 32 + 255) / 256;

    const __half* w0 = wf_p;
    const __half* w1 = wf_p + FD * FD;
    const __half* w2 = wf_p + 2 * FD * FD;
    const __half* w3 = wf_p + 3 * FD * FD;

    // ---- layer 1
    k_gemm_mma<<<ggrid, 256, SMEM_GEMM>>>(x, w0, w1, xlh_p, xr_p);
    k_gat_aggregate<<<egrid, 256>>>(xlh_p, xr_p, att1, b1, h_p);
    // ---- layer 2 (fc fused into aggregate epilogue)
    k_gemm_mma<<<ggrid, 256, SMEM_GEMM>>>(h_p, w2, w3, xlh_p, xr_p);
    k_gat_fc<<<egrid, 256>>>(xlh_p, xr_p, att2, b2, Wfc, bfc, out);
}

// round 10
// speedup vs baseline: 1.8985x; 1.2182x over previous
#include <cuda_runtime.h>
#include <cuda_fp16.h>
#include <math.h>
#include <stdint.h>

// Problem constants
#define NN 50000
#define EE 800000
#define FD 128              // H*C = 128 features
#define NCLS 10
#define SLOPE 0.2f

// ---------------- scratch (static device allocations; no cudaMalloc) ----------
__device__ __half g_xlh[NN * FD];   // source-transformed features (Wl), fp16
__device__ float g_xr[NN * FD];     // target-transformed features (Wr)
__device__ float g_h[NN * FD];      // layer output / next layer input
__device__ __half g_wf[4][FD * FD]; // fp16 weights, transposed [n][k]
__device__ int   g_deg[NN];         // edge-only in-degree (self loop handled inline)
__device__ int   g_off[NN];
__device__ int   g_cur[NN];
__device__ int   g_csr[EE];         // src node id per CSR slot (grouped by dst)
#define NCHUNK 49                   // ceil(50000/1024)
__device__ int   g_chunk[NCHUNK];

// ---------------- CSR construction -------------------------------------------
__global__ void k_count(const int* __restrict__ ei) {
    int i = blockIdx.x * blockDim.x + threadIdx.x;
    if (i < EE) atomicAdd(&g_deg[ei[EE + i]], 1);   // dst row
}

__global__ void k_scan1() {
    __shared__ int sh[1024];
    int i = blockIdx.x * 1024 + threadIdx.x;
    int v = (i < NN) ? g_deg[i] : 0;
    sh[threadIdx.x] = v;
    __syncthreads();
    for (int ofs = 1; ofs < 1024; ofs <<= 1) {
        int t = (threadIdx.x >= ofs) ? sh[threadIdx.x - ofs] : 0;
        __syncthreads();
        sh[threadIdx.x] += t;
        __syncthreads();
    }
    if (i < NN) g_off[i] = sh[threadIdx.x];         // inclusive within chunk
    if (threadIdx.x == 1023) g_chunk[blockIdx.x] = sh[1023];
}

// chunk-prefix folded in: every block scans the 49 chunk totals locally
__global__ void k_scan3() {
    __shared__ int chpre[NCHUNK];
    if (threadIdx.x == 0) {
        int run = 0;
        for (int c = 0; c < NCHUNK; c++) { chpre[c] = run; run += g_chunk[c]; }
    }
    __syncthreads();
    int i = blockIdx.x * blockDim.x + threadIdx.x;
    if (i < NN) {
        int start = g_off[i] - g_deg[i] + chpre[i >> 10];  // exclusive global start
        g_off[i] = start;
        g_cur[i] = start;
    }
}

__global__ void k_fill(const int* __restrict__ ei) {
    int i = blockIdx.x * blockDim.x + threadIdx.x;
    if (i >= EE) return;
    int s = ei[i], d = ei[EE + i];
    int p = atomicAdd(&g_cur[d], 1);
    g_csr[p] = s;
}

// ---------------- weight prep: fp16, transposed to [n][k] --------------------
__global__ void k_prep_w(const float* __restrict__ Wa, const float* __restrict__ Wb,
                         const float* __restrict__ Wc, const float* __restrict__ Wd) {
    const float* W = (blockIdx.x == 0) ? Wa : (blockIdx.x == 1) ? Wb
                   : (blockIdx.x == 2) ? Wc : Wd;
    __half* O = g_wf[blockIdx.x];
    for (int e = threadIdx.x; e < FD * FD; e += blockDim.x) {
        int k = e >> 7, n = e & 127;      // W row-major [k][n]
        O[n * 128 + k] = __float2half_rn(W[e]);
    }
}

// ---------------- fp16 mma.sync dual GEMM ------------------------------------
// One CTA: 128 rows of X; O0 = X@W0 -> fp16 (xl), O1 = X@W1 -> fp32 (xr).
// SMEM fp16, pitch 136: [A][W0][W1], 34816 B each. NO occupancy clamp: ~180
// regs needed; forcing 2 CTAs/SM (128-reg cap) caused spills in R9.
#define APITCH 136
#define AB     (128 * APITCH * 2)     // 34816 bytes per array
#define SMEM_GEMM (3 * AB)            // 104448

#define MMA16816F(c, a, b0, b1)                                            \
    asm volatile("mma.sync.aligned.m16n8k16.row.col.f32.f16.f16.f32 "      \
                 "{%0,%1,%2,%3}, {%4,%5,%6,%7}, {%8,%9}, {%0,%1,%2,%3};"   \
                 : "+f"(c[0]), "+f"(c[1]), "+f"(c[2]), "+f"(c[3])          \
                 : "r"(a[0]), "r"(a[1]), "r"(a[2]), "r"(a[3]),             \
                   "r"(b0), "r"(b1))

__global__ __launch_bounds__(256)
void k_gemm_mma(const float* __restrict__ X,
                const __half* __restrict__ W0, const __half* __restrict__ W1,
                __half* __restrict__ O0, float* __restrict__ O1) {
    extern __shared__ char sm[];
    __half* A = (__half*)(sm);
    int tid = threadIdx.x;
    int r0 = blockIdx.x * 128;

    // ---- load X tile -> fp16
    const float4* X4 = (const float4*)X;
#pragma unroll
    for (int j = 0; j < 16; j++) {
        int e = tid + j * 256;            // 0..4095
        int row = e >> 5, q = e & 31;
        float4 v = make_float4(0.f, 0.f, 0.f, 0.f);
        if (r0 + row < NN) v = X4[(size_t)(r0 + row) * 32 + q];
        __half2 p0 = __floats2half2_rn(v.x, v.y);
        __half2 p1 = __floats2half2_rn(v.z, v.w);
        int base = row * APITCH + q * 4;
        *(__half2*)&A[base]     = p0;
        *(__half2*)&A[base + 2] = p1;
    }

    // ---- copy weights (dense [n][128] fp16) into pitched SMEM
    {
        const uint4* src[2] = {(const uint4*)W0, (const uint4*)W1};
#pragma unroll
        for (int a = 0; a < 2; a++) {
            char* dst = sm + (1 + a) * AB;
#pragma unroll
            for (int j = 0; j < 8; j++) {
                int e = tid + j * 256;        // 0..2047 uint4
                int n = e >> 4, kq = e & 15;  // kq*8 fp16 = 16 B
                *(uint4*)(dst + n * (APITCH * 2) + kq * 16) = src[a][e];
            }
        }
    }
    __syncthreads();

    // ---- warp layout: 2 (M) x 4 (N); warp tile 64 x 64
    int lane = tid & 31, wid = tid >> 5;
    int g = lane >> 2, t = lane & 3;
    int wm = (wid & 1) * 64;
    int wn = wid >> 1;
    int bsel = wn >> 1;                   // 0 -> W0 (xl/fp16), 1 -> W1 (xr/fp32)
    int nb = (wn & 1) * 64;
    const __half* B = (const __half*)(sm + (1 + bsel) * AB);

    float acc[4][8][4];
#pragma unroll
    for (int mi = 0; mi < 4; mi++)
#pragma unroll
        for (int ni = 0; ni < 8; ni++)
#pragma unroll
            for (int q = 0; q < 4; q++) acc[mi][ni][q] = 0.f;

#pragma unroll
    for (int kk = 0; kk < 8; kk++) {
        int k0 = kk * 16;
        uint32_t ah[4][4];
#pragma unroll
        for (int mi = 0; mi < 4; mi++) {
            int rb = wm + mi * 16;
            ah[mi][0] = *(const uint32_t*)&A[(rb + g)     * APITCH + k0 + 2 * t];
            ah[mi][1] = *(const uint32_t*)&A[(rb + g + 8) * APITCH + k0 + 2 * t];
            ah[mi][2] = *(const uint32_t*)&A[(rb + g)     * APITCH + k0 + 2 * t + 8];
            ah[mi][3] = *(const uint32_t*)&A[(rb + g + 8) * APITCH + k0 + 2 * t + 8];
        }
#pragma unroll
        for (int ni = 0; ni < 8; ni++) {
            int col = nb + ni * 8 + g;
            uint32_t b0 = *(const uint32_t*)&B[col * APITCH + k0 + 2 * t];
            uint32_t b1 = *(const uint32_t*)&B[col * APITCH + k0 + 2 * t + 8];
#pragma unroll
            for (int mi = 0; mi < 4; mi++)
                MMA16816F(acc[mi][ni], ah[mi], b0, b1);
        }
    }

    // ---- epilogue
#pragma unroll
    for (int mi = 0; mi < 4; mi++) {
        int row = r0 + wm + mi * 16 + g;
#pragma unroll
        for (int ni = 0; ni < 8; ni++) {
            int colg = nb + ni * 8 + 2 * t;
            if (bsel == 0) {
                if (row < NN)
                    *(__half2*)&O0[(size_t)row * FD + colg] =
                        __floats2half2_rn(acc[mi][ni][0], acc[mi][ni][1]);
                if (row + 8 < NN)
                    *(__half2*)&O0[(size_t)(row + 8) * FD + colg] =
                        __floats2half2_rn(acc[mi][ni][2], acc[mi][ni][3]);
            } else {
                if (row < NN)
                    *(float2*)&O1[(size_t)row * FD + colg] =
                        make_float2(acc[mi][ni][0], acc[mi][ni][1]);
                if (row + 8 < NN)
                    *(float2*)&O1[(size_t)(row + 8) * FD + colg] =
                        make_float2(acc[mi][ni][2], acc[mi][ni][3]);
            }
        }
    }
}

// ---------------- GATv2 edge core: warp per dst node, online softmax ----------
// Self loop handled inline (no CSR slot); edge list is edges only.
__device__ __forceinline__ float leaky_dot(float4 xv, float4 xr4, float4 a4) {
    float ex = xv.x + xr4.x; ex = (ex > 0.f) ? ex : SLOPE * ex;
    float ey = xv.y + xr4.y; ey = (ey > 0.f) ? ey : SLOPE * ey;
    float ez = xv.z + xr4.z; ez = (ez > 0.f) ? ez : SLOPE * ez;
    float ew = xv.w + xr4.w; ew = (ew > 0.f) ? ew : SLOPE * ew;
    float p = ex * a4.x + ey * a4.y + ez * a4.z + ew * a4.w;
    p += __shfl_xor_sync(0xffffffffu, p, 1);
    p += __shfl_xor_sync(0xffffffffu, p, 2);
    return p;
}

__device__ __forceinline__ float4 h2f4(uint2 r) {
    float2 f0 = __half22float2(*(__half2*)&r.x);
    float2 f1 = __half22float2(*(__half2*)&r.y);
    return make_float4(f0.x, f0.y, f1.x, f1.y);
}

__device__ __forceinline__ float4 gat_node(const __half* __restrict__ xl,
                                           const float* __restrict__ xr,
                                           const float* __restrict__ att,
                                           const float* __restrict__ bias,
                                           int v, int l) {
    float4 xr4 = *(const float4*)(xr + (size_t)v * FD + l * 4);
    float4 a4  = *(const float4*)(att + l * 4);
    int beg = g_off[v];
    int cnt = g_deg[v];                       // edge count (may be 0)

    // self message first (always present)
    float4 xs = h2f4(*(const uint2*)(xl + (size_t)v * FD + l * 4));
    float m = leaky_dot(xs, xr4, a4);
    float den = 1.f;
    float4 acc = xs;

    // 2-deep prefetch pipeline over incoming edges
    uint2 r0v, r1v;
    if (cnt > 0) r0v = *(const uint2*)(xl + (size_t)g_csr[beg] * FD + l * 4);
    if (cnt > 1) r1v = *(const uint2*)(xl + (size_t)g_csr[beg + 1] * FD + l * 4);

    for (int j = 0; j < cnt; j++) {
        uint2 rv = r0v;
        r0v = r1v;
        if (j + 2 < cnt)
            r1v = *(const uint2*)(xl + (size_t)g_csr[beg + j + 2] * FD + l * 4);
        float4 xv = h2f4(rv);
        float p = leaky_dot(xv, xr4, a4);
        float nm = fmaxf(m, p);
        float wo = __expf(m - nm);
        float wn = __expf(p - nm);
        den = den * wo + wn;
        acc.x = acc.x * wo + wn * xv.x;
        acc.y = acc.y * wo + wn * xv.y;
        acc.z = acc.z * wo + wn * xv.z;
        acc.w = acc.w * wo + wn * xv.w;
        m = nm;
    }

    float inv = 1.0f / den;
    float4 b4 = *(const float4*)(bias + l * 4);
    float4 o;
    o.x = fmaxf(acc.x * inv + b4.x, 0.f);     // fused bias + relu
    o.y = fmaxf(acc.y * inv + b4.y, 0.f);
    o.z = fmaxf(acc.z * inv + b4.z, 0.f);
    o.w = fmaxf(acc.w * inv + b4.w, 0.f);
    return o;
}

__global__ void k_gat_aggregate(const __half* __restrict__ xl,
                                const float* __restrict__ xr,
                                const float* __restrict__ att,
                                const float* __restrict__ bias,
                                float* __restrict__ out) {
    int gtid = blockIdx.x * blockDim.x + threadIdx.x;
    int v = gtid >> 5;
    int l = threadIdx.x & 31;
    if (v >= NN) return;
    float4 o = gat_node(xl, xr, att, bias, v, l);
    *(float4*)(out + (size_t)v * FD + l * 4) = o;
}

// Layer-2 aggregate with fused fc_out epilogue
__global__ void k_gat_fc(const __half* __restrict__ xl,
                         const float* __restrict__ xr,
                         const float* __restrict__ att,
                         const float* __restrict__ bias,
                         const float* __restrict__ Wfc,
                         const float* __restrict__ bfc,
                         float* __restrict__ out) {
    __shared__ float Ws[FD * NCLS];
    __shared__ float bs[NCLS];
    for (int i = threadIdx.x; i < FD * NCLS; i += blockDim.x) Ws[i] = Wfc[i];
    if (threadIdx.x < NCLS) bs[threadIdx.x] = bfc[threadIdx.x];
    __syncthreads();

    int gtid = blockIdx.x * blockDim.x + threadIdx.x;
    int v = gtid >> 5;
    int l = threadIdx.x & 31;
    if (v >= NN) return;
    float4 o = gat_node(xl, xr, att, bias, v, l);

#pragma unroll
    for (int c = 0; c < NCLS; c++) {
        float p = o.x * Ws[(l * 4 + 0) * NCLS + c]
                + o.y * Ws[(l * 4 + 1) * NCLS + c]
                + o.z * Ws[(l * 4 + 2) * NCLS + c]
                + o.w * Ws[(l * 4 + 3) * NCLS + c];
        p += __shfl_xor_sync(0xffffffffu, p, 16);
        p += __shfl_xor_sync(0xffffffffu, p, 8);
        p += __shfl_xor_sync(0xffffffffu, p, 4);
        p += __shfl_xor_sync(0xffffffffu, p, 2);
        p += __shfl_xor_sync(0xffffffffu, p, 1);
        if (l == c) out[(size_t)v * NCLS + c] = p + bs[c];
    }
}

// ---------------- launch ------------------------------------------------------
extern "C" void kernel_launch(void* const* d_in, const int* in_sizes, int n_in,
                              void* d_out, int out_size) {
    const float* x    = (const float*)d_in[0];
    const int*   ei   = (const int*)  d_in[1];
    const float* Wl1  = (const float*)d_in[2];
    const float* Wr1  = (const float*)d_in[3];
    const float* att1 = (const float*)d_in[4];
    const float* b1   = (const float*)d_in[5];
    const float* Wl2  = (const float*)d_in[6];
    const float* Wr2  = (const float*)d_in[7];
    const float* att2 = (const float*)d_in[8];
    const float* b2   = (const float*)d_in[9];
    const float* Wfc  = (const float*)d_in[10];
    const float* bfc  = (const float*)d_in[11];
    float* out = (float*)d_out;

    float *xr_p, *h_p;
    __half *xlh_p, *wf_p;
    int *deg_p;
    cudaGetSymbolAddress((void**)&xlh_p, g_xlh);
    cudaGetSymbolAddress((void**)&xr_p,  g_xr);
    cudaGetSymbolAddress((void**)&h_p,   g_h);
    cudaGetSymbolAddress((void**)&wf_p,  g_wf);
    cudaGetSymbolAddress((void**)&deg_p, g_deg);

    cudaFuncSetAttribute(k_gemm_mma, cudaFuncAttributeMaxDynamicSharedMemorySize, SMEM_GEMM);

    // ---- CSR build (self loops excluded; handled inline) + weight prep
    cudaMemsetAsync(deg_p, 0, NN * sizeof(int));
    k_count<<<(EE + 255) / 256, 256>>>(ei);
    k_scan1<<<NCHUNK, 1024>>>();
    k_scan3<<<(NN + 255) / 256, 256>>>();
    k_fill<<<(EE + 255) / 256, 256>>>(ei);
    k_prep_w<<<4, 256>>>(Wl1, Wr1, Wl2, Wr2);

    int ggrid = (NN + 127) / 128;
    int egrid = (NN * 32 + 255) / 256;

    const __half* w0 = wf_p;
    const __half* w1 = wf_p + FD * FD;
    const __half* w2 = wf_p + 2 * FD * FD;
    const __half* w3 = wf_p + 3 * FD * FD;

    // ---- layer 1
    k_gemm_mma<<<ggrid, 256, SMEM_GEMM>>>(x, w0, w1, xlh_p, xr_p);
    k_gat_aggregate<<<egrid, 256>>>(xlh_p, xr_p, att1, b1, h_p);
    // ---- layer 2 (fc fused into aggregate epilogue)
    k_gemm_mma<<<ggrid, 256, SMEM_GEMM>>>(h_p, w2, w3, xlh_p, xr_p);
    k_gat_fc<<<egrid, 256>>>(xlh_p, xr_p, att2, b2, Wfc, bfc, out);
}

// round 11
// speedup vs baseline: 1.9820x; 1.0440x over previous
#include <cuda_runtime.h>
#include <cuda_fp16.h>
#include <math.h>
#include <stdint.h>

// Problem constants
#define NN 50000
#define EE 800000
#define FD 128              // H*C = 128 features
#define NCLS 10
#define SLOPE 0.2f

// ---------------- scratch (static device allocations; no cudaMalloc) ----------
__device__ __half g_xlh[NN * FD];   // source-transformed features (Wl), fp16
__device__ float g_xr[NN * FD];     // target-transformed features (Wr)
__device__ float g_h[NN * FD];      // layer output / next layer input
__device__ __half g_wf[4][FD * FD]; // fp16 weights, transposed [n][k]
__device__ int   g_deg[NN];         // edge-only in-degree (self loop handled inline)
__device__ int   g_off[NN];
__device__ int   g_cur[NN];
__device__ int   g_csr[EE];         // src node id per CSR slot (grouped by dst)
#define NCHUNK 49                   // ceil(50000/1024)
__device__ int   g_chunk[NCHUNK];

// ---------------- CSR construction -------------------------------------------
__global__ void k_count(const int* __restrict__ ei) {
    int i = blockIdx.x * blockDim.x + threadIdx.x;
    if (i < EE) atomicAdd(&g_deg[ei[EE + i]], 1);   // dst row
}

__global__ void k_scan1() {
    __shared__ int sh[1024];
    int i = blockIdx.x * 1024 + threadIdx.x;
    int v = (i < NN) ? g_deg[i] : 0;
    sh[threadIdx.x] = v;
    __syncthreads();
    for (int ofs = 1; ofs < 1024; ofs <<= 1) {
        int t = (threadIdx.x >= ofs) ? sh[threadIdx.x - ofs] : 0;
        __syncthreads();
        sh[threadIdx.x] += t;
        __syncthreads();
    }
    if (i < NN) g_off[i] = sh[threadIdx.x];         // inclusive within chunk
    if (threadIdx.x == 1023) g_chunk[blockIdx.x] = sh[1023];
}

// chunk-prefix folded in: every block scans the 49 chunk totals locally
__global__ void k_scan3() {
    __shared__ int chpre[NCHUNK];
    if (threadIdx.x == 0) {
        int run = 0;
        for (int c = 0; c < NCHUNK; c++) { chpre[c] = run; run += g_chunk[c]; }
    }
    __syncthreads();
    int i = blockIdx.x * blockDim.x + threadIdx.x;
    if (i < NN) {
        int start = g_off[i] - g_deg[i] + chpre[i >> 10];  // exclusive global start
        g_off[i] = start;
        g_cur[i] = start;
    }
}

__global__ void k_fill(const int* __restrict__ ei) {
    int i = blockIdx.x * blockDim.x + threadIdx.x;
    if (i >= EE) return;
    int s = ei[i], d = ei[EE + i];
    int p = atomicAdd(&g_cur[d], 1);
    g_csr[p] = s;
}

// ---------------- weight prep: fp16, transposed to [n][k] --------------------
__global__ void k_prep_w(const float* __restrict__ Wa, const float* __restrict__ Wb,
                         const float* __restrict__ Wc, const float* __restrict__ Wd) {
    const float* W = (blockIdx.x == 0) ? Wa : (blockIdx.x == 1) ? Wb
                   : (blockIdx.x == 2) ? Wc : Wd;
    __half* O = g_wf[blockIdx.x];
    for (int e = threadIdx.x; e < FD * FD; e += blockDim.x) {
        int k = e >> 7, n = e & 127;      // W row-major [k][n]
        O[n * 128 + k] = __float2half_rn(W[e]);
    }
}

// ---------------- fp16 mma.sync dual GEMM ------------------------------------
#define APITCH 136
#define AB     (128 * APITCH * 2)     // 34816 bytes per array
#define SMEM_GEMM (3 * AB)            // 104448

#define MMA16816F(c, a, b0, b1)                                            \
    asm volatile("mma.sync.aligned.m16n8k16.row.col.f32.f16.f16.f32 "      \
                 "{%0,%1,%2,%3}, {%4,%5,%6,%7}, {%8,%9}, {%0,%1,%2,%3};"   \
                 : "+f"(c[0]), "+f"(c[1]), "+f"(c[2]), "+f"(c[3])          \
                 : "r"(a[0]), "r"(a[1]), "r"(a[2]), "r"(a[3]),             \
                   "r"(b0), "r"(b1))

__global__ __launch_bounds__(256)
void k_gemm_mma(const float* __restrict__ X,
                const __half* __restrict__ W0, const __half* __restrict__ W1,
                __half* __restrict__ O0, float* __restrict__ O1) {
    extern __shared__ char sm[];
    __half* A = (__half*)(sm);
    int tid = threadIdx.x;
    int r0 = blockIdx.x * 128;

    // ---- load X tile -> fp16
    const float4* X4 = (const float4*)X;
#pragma unroll
    for (int j = 0; j < 16; j++) {
        int e = tid + j * 256;            // 0..4095
        int row = e >> 5, q = e & 31;
        float4 v = make_float4(0.f, 0.f, 0.f, 0.f);
        if (r0 + row < NN) v = X4[(size_t)(r0 + row) * 32 + q];
        __half2 p0 = __floats2half2_rn(v.x, v.y);
        __half2 p1 = __floats2half2_rn(v.z, v.w);
        int base = row * APITCH + q * 4;
        *(__half2*)&A[base]     = p0;
        *(__half2*)&A[base + 2] = p1;
    }

    // ---- copy weights (dense [n][128] fp16) into pitched SMEM
    {
        const uint4* src[2] = {(const uint4*)W0, (const uint4*)W1};
#pragma unroll
        for (int a = 0; a < 2; a++) {
            char* dst = sm + (1 + a) * AB;
#pragma unroll
            for (int j = 0; j < 8; j++) {
                int e = tid + j * 256;        // 0..2047 uint4
                int n = e >> 4, kq = e & 15;  // kq*8 fp16 = 16 B
                *(uint4*)(dst + n * (APITCH * 2) + kq * 16) = src[a][e];
            }
        }
    }
    __syncthreads();

    // ---- warp layout: 2 (M) x 4 (N); warp tile 64 x 64
    int lane = tid & 31, wid = tid >> 5;
    int g = lane >> 2, t = lane & 3;
    int wm = (wid & 1) * 64;
    int wn = wid >> 1;
    int bsel = wn >> 1;                   // 0 -> W0 (xl/fp16), 1 -> W1 (xr/fp32)
    int nb = (wn & 1) * 64;
    const __half* B = (const __half*)(sm + (1 + bsel) * AB);

    float acc[4][8][4];
#pragma unroll
    for (int mi = 0; mi < 4; mi++)
#pragma unroll
        for (int ni = 0; ni < 8; ni++)
#pragma unroll
            for (int q = 0; q < 4; q++) acc[mi][ni][q] = 0.f;

#pragma unroll
    for (int kk = 0; kk < 8; kk++) {
        int k0 = kk * 16;
        uint32_t ah[4][4];
#pragma unroll
        for (int mi = 0; mi < 4; mi++) {
            int rb = wm + mi * 16;
            ah[mi][0] = *(const uint32_t*)&A[(rb + g)     * APITCH + k0 + 2 * t];
            ah[mi][1] = *(const uint32_t*)&A[(rb + g + 8) * APITCH + k0 + 2 * t];
            ah[mi][2] = *(const uint32_t*)&A[(rb + g)     * APITCH + k0 + 2 * t + 8];
            ah[mi][3] = *(const uint32_t*)&A[(rb + g + 8) * APITCH + k0 + 2 * t + 8];
        }
#pragma unroll
        for (int ni = 0; ni < 8; ni++) {
            int col = nb + ni * 8 + g;
            uint32_t b0 = *(const uint32_t*)&B[col * APITCH + k0 + 2 * t];
            uint32_t b1 = *(const uint32_t*)&B[col * APITCH + k0 + 2 * t + 8];
#pragma unroll
            for (int mi = 0; mi < 4; mi++)
                MMA16816F(acc[mi][ni], ah[mi], b0, b1);
        }
    }

    // ---- epilogue
#pragma unroll
    for (int mi = 0; mi < 4; mi++) {
        int row = r0 + wm + mi * 16 + g;
#pragma unroll
        for (int ni = 0; ni < 8; ni++) {
            int colg = nb + ni * 8 + 2 * t;
            if (bsel == 0) {
                if (row < NN)
                    *(__half2*)&O0[(size_t)row * FD + colg] =
                        __floats2half2_rn(acc[mi][ni][0], acc[mi][ni][1]);
                if (row + 8 < NN)
                    *(__half2*)&O0[(size_t)(row + 8) * FD + colg] =
                        __floats2half2_rn(acc[mi][ni][2], acc[mi][ni][3]);
            } else {
                if (row < NN)
                    *(float2*)&O1[(size_t)row * FD + colg] =
                        make_float2(acc[mi][ni][0], acc[mi][ni][1]);
                if (row + 8 < NN)
                    *(float2*)&O1[(size_t)(row + 8) * FD + colg] =
                        make_float2(acc[mi][ni][2], acc[mi][ni][3]);
            }
        }
    }
}

// ---------------- GATv2 edge core: warp per dst, 4-edge batched softmax -------
__device__ __forceinline__ float leaky_dot(float4 xv, float4 xr4, float4 a4) {
    float ex = xv.x + xr4.x; ex = (ex > 0.f) ? ex : SLOPE * ex;
    float ey = xv.y + xr4.y; ey = (ey > 0.f) ? ey : SLOPE * ey;
    float ez = xv.z + xr4.z; ez = (ez > 0.f) ? ez : SLOPE * ez;
    float ew = xv.w + xr4.w; ew = (ew > 0.f) ? ew : SLOPE * ew;
    float p = ex * a4.x + ey * a4.y + ez * a4.z + ew * a4.w;
    p += __shfl_xor_sync(0xffffffffu, p, 1);
    p += __shfl_xor_sync(0xffffffffu, p, 2);
    return p;
}

__device__ __forceinline__ float4 h2f4(uint2 r) {
    float2 f0 = __half22float2(*(__half2*)&r.x);
    float2 f1 = __half22float2(*(__half2*)&r.y);
    return make_float4(f0.x, f0.y, f1.x, f1.y);
}

__device__ __forceinline__ float4 gat_node(const __half* __restrict__ xl,
                                           const float* __restrict__ xr,
                                           const float* __restrict__ att,
                                           const float* __restrict__ bias,
                                           int v, int l) {
    float4 xr4 = *(const float4*)(xr + (size_t)v * FD + l * 4);
    float4 a4  = *(const float4*)(att + l * 4);
    int beg = g_off[v];
    int cnt = g_deg[v];                       // edge count (may be 0)

    // self message first (always present)
    float4 xs = h2f4(*(const uint2*)(xl + (size_t)v * FD + l * 4));
    float m = leaky_dot(xs, xr4, a4);
    float den = 1.f;
    float4 acc = xs;

    // 4-edge batches: 4 independent gathers + score chains per iteration,
    // ONE combined online-softmax update (breaks the per-edge serial chain).
    for (int j = 0; j < cnt; j += 4) {
        float4 xv0 = make_float4(0.f, 0.f, 0.f, 0.f), xv1 = xv0, xv2 = xv0, xv3 = xv0;
        if (j     < cnt) xv0 = h2f4(*(const uint2*)(xl + (size_t)g_csr[beg + j]     * FD + l * 4));
        if (j + 1 < cnt) xv1 = h2f4(*(const uint2*)(xl + (size_t)g_csr[beg + j + 1] * FD + l * 4));
        if (j + 2 < cnt) xv2 = h2f4(*(const uint2*)(xl + (size_t)g_csr[beg + j + 2] * FD + l * 4));
        if (j + 3 < cnt) xv3 = h2f4(*(const uint2*)(xl + (size_t)g_csr[beg + j + 3] * FD + l * 4));

        float p0 = leaky_dot(xv0, xr4, a4);
        float p1 = leaky_dot(xv1, xr4, a4);
        float p2 = leaky_dot(xv2, xr4, a4);
        float p3 = leaky_dot(xv3, xr4, a4);
        if (j + 1 >= cnt) p1 = -1e30f;        // invalid slots -> weight 0
        if (j + 2 >= cnt) p2 = -1e30f;
        if (j + 3 >= cnt) p3 = -1e30f;

        float pm = fmaxf(fmaxf(p0, p1), fmaxf(p2, p3));
        float nm = fmaxf(m, pm);
        float wo = __expf(m - nm);
        float w0 = __expf(p0 - nm);
        float w1 = __expf(p1 - nm);
        float w2 = __expf(p2 - nm);
        float w3 = __expf(p3 - nm);
        den = den * wo + ((w0 + w1) + (w2 + w3));
        acc.x = acc.x * wo + ((w0 * xv0.x + w1 * xv1.x) + (w2 * xv2.x + w3 * xv3.x));
        acc.y = acc.y * wo + ((w0 * xv0.y + w1 * xv1.y) + (w2 * xv2.y + w3 * xv3.y));
        acc.z = acc.z * wo + ((w0 * xv0.z + w1 * xv1.z) + (w2 * xv2.z + w3 * xv3.z));
        acc.w = acc.w * wo + ((w0 * xv0.w + w1 * xv1.w) + (w2 * xv2.w + w3 * xv3.w));
        m = nm;
    }

    float inv = 1.0f / den;
    float4 b4 = *(const float4*)(bias + l * 4);
    float4 o;
    o.x = fmaxf(acc.x * inv + b4.x, 0.f);     // fused bias + relu
    o.y = fmaxf(acc.y * inv + b4.y, 0.f);
    o.z = fmaxf(acc.z * inv + b4.z, 0.f);
    o.w = fmaxf(acc.w * inv + b4.w, 0.f);
    return o;
}

__global__ void k_gat_aggregate(const __half* __restrict__ xl,
                                const float* __restrict__ xr,
                                const float* __restrict__ att,
                                const float* __restrict__ bias,
                                float* __restrict__ out) {
    int gtid = blockIdx.x * blockDim.x + threadIdx.x;
    int v = gtid >> 5;
    int l = threadIdx.x & 31;
    if (v >= NN) return;
    float4 o = gat_node(xl, xr, att, bias, v, l);
    *(float4*)(out + (size_t)v * FD + l * 4) = o;
}

// Layer-2 aggregate with fused fc_out epilogue
__global__ void k_gat_fc(const __half* __restrict__ xl,
                         const float* __restrict__ xr,
                         const float* __restrict__ att,
                         const float* __restrict__ bias,
                         const float* __restrict__ Wfc,
                         const float* __restrict__ bfc,
                         float* __restrict__ out) {
    __shared__ float Ws[FD * NCLS];
    __shared__ float bs[NCLS];
    for (int i = threadIdx.x; i < FD * NCLS; i += blockDim.x) Ws[i] = Wfc[i];
    if (threadIdx.x < NCLS) bs[threadIdx.x] = bfc[threadIdx.x];
    __syncthreads();

    int gtid = blockIdx.x * blockDim.x + threadIdx.x;
    int v = gtid >> 5;
    int l = threadIdx.x & 31;
    if (v >= NN) return;
    float4 o = gat_node(xl, xr, att, bias, v, l);

#pragma unroll
    for (int c = 0; c < NCLS; c++) {
        float p = o.x * Ws[(l * 4 + 0) * NCLS + c]
                + o.y * Ws[(l * 4 + 1) * NCLS + c]
                + o.z * Ws[(l * 4 + 2) * NCLS + c]
                + o.w * Ws[(l * 4 + 3) * NCLS + c];
        p += __shfl_xor_sync(0xffffffffu, p, 16);
        p += __shfl_xor_sync(0xffffffffu, p, 8);
        p += __shfl_xor_sync(0xffffffffu, p, 4);
        p += __shfl_xor_sync(0xffffffffu, p, 2);
        p += __shfl_xor_sync(0xffffffffu, p, 1);
        if (l == c) out[(size_t)v * NCLS + c] = p + bs[c];
    }
}

// ---------------- launch ------------------------------------------------------
extern "C" void kernel_launch(void* const* d_in, const int* in_sizes, int n_in,
                              void* d_out, int out_size) {
    const float* x    = (const float*)d_in[0];
    const int*   ei   = (const int*)  d_in[1];
    const float* Wl1  = (const float*)d_in[2];
    const float* Wr1  = (const float*)d_in[3];
    const float* att1 = (const float*)d_in[4];
    const float* b1   = (const float*)d_in[5];
    const float* Wl2  = (const float*)d_in[6];
    const float* Wr2  = (const float*)d_in[7];
    const float* att2 = (const float*)d_in[8];
    const float* b2   = (const float*)d_in[9];
    const float* Wfc  = (const float*)d_in[10];
    const float* bfc  = (const float*)d_in[11];
    float* out = (float*)d_out;

    float *xr_p, *h_p;
    __half *xlh_p, *wf_p;
    int *deg_p;
    cudaGetSymbolAddress((void**)&xlh_p, g_xlh);
    cudaGetSymbolAddress((void**)&xr_p,  g_xr);
    cudaGetSymbolAddress((void**)&h_p,   g_h);
    cudaGetSymbolAddress((void**)&wf_p,  g_wf);
    cudaGetSymbolAddress((void**)&deg_p, g_deg);

    cudaFuncSetAttribute(k_gemm_mma, cudaFuncAttributeMaxDynamicSharedMemorySize, SMEM_GEMM);

    // ---- CSR build (self loops excluded; handled inline) + weight prep
    cudaMemsetAsync(deg_p, 0, NN * sizeof(int));
    k_count<<<(EE + 255) / 256, 256>>>(ei);
    k_scan1<<<NCHUNK, 1024>>>();
    k_scan3<<<(NN + 255) / 256, 256>>>();
    k_fill<<<(EE + 255) / 256, 256>>>(ei);
    k_prep_w<<<4, 256>>>(Wl1, Wr1, Wl2, Wr2);

    int ggrid = (NN + 127) / 128;
    int egrid = (NN * 32 + 255) / 256;

    const __half* w0 = wf_p;
    const __half* w1 = wf_p + FD * FD;
    const __half* w2 = wf_p + 2 * FD * FD;
    const __half* w3 = wf_p + 3 * FD * FD;

    // ---- layer 1
    k_gemm_mma<<<ggrid, 256, SMEM_GEMM>>>(x, w0, w1, xlh_p, xr_p);
    k_gat_aggregate<<<egrid, 256>>>(xlh_p, xr_p, att1, b1, h_p);
    // ---- layer 2 (fc fused into aggregate epilogue)
    k_gemm_mma<<<ggrid, 256, SMEM_GEMM>>>(h_p, w2, w3, xlh_p, xr_p);
    k_gat_fc<<<egrid, 256>>>(xlh_p, xr_p, att2, b2, Wfc, bfc, out);
}